// round 5
// baseline (speedup 1.0000x reference)
#include <cuda_runtime.h>
#include <cuda_bf16.h>
#include <math.h>

// Problem constants
#define BB 16
#define EE 25
#define TT 300
#define CC 3
#define DD 64
#define HH 8
#define FFD 256
#define LL 4
#define NCLS 60
#define NN (BB*EE)        // 400
#define SS (TT+1)         // 301
#define HD (DD/HH)        // 8
#define MROWS (NN*SS)     // 120400
#define EPS 1e-5f

// ---------------- scratch buffers -------------------------------------------
__device__ float g_h[MROWS*DD];      // residual stream
__device__ float g_y[MROWS*DD];      // LN output (layer-0 qkv input only)
__device__ float g_qkv[MROWS*3*DD];  // qkv
__device__ float g_o[MROWS*DD];      // attention output
__device__ float g_feat[BB*DD];
__device__ float g_feat2[BB*DD];

// ---------------- helpers ---------------------------------------------------
__device__ __forceinline__ float warp_sum(float v) {
    #pragma unroll
    for (int o = 16; o; o >>= 1) v += __shfl_xor_sync(0xffffffffu, v, o);
    return v;
}

__device__ __forceinline__ float gelu_exact(float x) {
    return 0.5f * x * (1.0f + erff(x * 0.70710678118654752f));
}

__device__ __forceinline__ void mma_tf32(float& c0, float& c1, float& c2, float& c3,
                                         unsigned a0, unsigned a1, unsigned a2, unsigned a3,
                                         unsigned b0, unsigned b1) {
    asm volatile(
        "mma.sync.aligned.m16n8k8.row.col.f32.tf32.tf32.f32 "
        "{%0,%1,%2,%3}, {%4,%5,%6,%7}, {%8,%9}, {%0,%1,%2,%3};"
        : "+f"(c0), "+f"(c1), "+f"(c2), "+f"(c3)
        : "r"(a0), "r"(a1), "r"(a2), "r"(a3), "r"(b0), "r"(b1));
}

#define ASWI(r,c) ((r)*64 + (((c) ^ (((r)&7)<<2))))

// ---------------- embed + LN + cls + pos + fused ln1[0] ----------------------
__global__ void embed_kernel(const float* __restrict__ x,
                             const float* __restrict__ ew,
                             const float* __restrict__ ebias,
                             const float* __restrict__ eg,
                             const float* __restrict__ ebt,
                             const float* __restrict__ cls,
                             const float* __restrict__ l1g,
                             const float* __restrict__ l1b) {
    int warp = (blockIdx.x * blockDim.x + threadIdx.x) >> 5;
    int lane = threadIdx.x & 31;
    if (warp >= MROWS) return;
    int n = warp / SS, s = warp % SS;
    int b = n / EE, e = n % EE;

    float v0, v1;
    if (s == 0) {
        v0 = cls[lane];
        v1 = cls[lane + 32];
    } else {
        int t = s - 1;
        float x0 = x[((b*CC + 0)*TT + t)*EE + e];
        float x1 = x[((b*CC + 1)*TT + t)*EE + e];
        float x2 = x[((b*CC + 2)*TT + t)*EE + e];
        int d0 = lane, d1 = lane + 32;
        v0 = ebias[d0] + x0*ew[d0*3] + x1*ew[d0*3+1] + x2*ew[d0*3+2];
        v1 = ebias[d1] + x0*ew[d1*3] + x1*ew[d1*3+1] + x2*ew[d1*3+2];
        float mu = warp_sum(v0 + v1) * (1.0f/64.0f);
        float a0 = v0 - mu, a1 = v1 - mu;
        float var = warp_sum(a0*a0 + a1*a1) * (1.0f/64.0f);
        float r = rsqrtf(var + EPS);
        v0 = a0 * r * eg[d0] + ebt[d0];
        v1 = a1 * r * eg[d1] + ebt[d1];
    }
    const float kfreq = -0.14391565f; // -ln(10000)/64
    {
        int d0 = lane;
        int i = d0 >> 1;
        float ang = (float)s * __expf((float)(2*i) * kfreq);
        v0 += (d0 & 1) ? cosf(ang) : sinf(ang);
        int d1 = lane + 32;
        i = d1 >> 1;
        ang = (float)s * __expf((float)(2*i) * kfreq);
        v1 += (d1 & 1) ? cosf(ang) : sinf(ang);
    }
    g_h[warp*DD + lane]      = v0;
    g_h[warp*DD + lane + 32] = v1;
    // fused ln1[0]
    float mu = warp_sum(v0 + v1) * (1.0f/64.0f);
    float a0 = v0 - mu, a1 = v1 - mu;
    float var = warp_sum(a0*a0 + a1*a1) * (1.0f/64.0f);
    float rs = rsqrtf(var + EPS);
    g_y[warp*DD + lane]      = a0*rs*l1g[lane]    + l1b[lane];
    g_y[warp*DD + lane + 32] = a1*rs*l1g[lane+32] + l1b[lane+32];
}

// ---------------- qkv GEMM (layer 0 only) ------------------------------------
__global__ void __launch_bounds__(256, 2)
qkv_gemm(const float* __restrict__ A, const float* __restrict__ W,
         const float* __restrict__ bias, float* __restrict__ out) {
    __shared__ unsigned As[128*64];
    __shared__ unsigned Bs[64*64];
    int tid = threadIdx.x;
    int warp = tid >> 5, lane = tid & 31;
    int wm = warp >> 1, wn = warp & 1;
    int row0 = blockIdx.x * 128;
    int qr = lane >> 2, qk = lane & 3;

    #pragma unroll
    for (int i = 0; i < 8; i++) {
        int idx = tid + i*256;
        int r = idx >> 4, c4 = (idx & 15) << 2;
        int gr = row0 + r;
        float4 v = (gr < MROWS) ? *(const float4*)(A + (size_t)gr*64 + c4)
                                : make_float4(0.f,0.f,0.f,0.f);
        *(float4*)(&As[ASWI(r, c4)]) = v;
    }

    for (int nt = 0; nt < 3; nt++) {
        if (nt) __syncthreads();
        #pragma unroll
        for (int i = 0; i < 4; i++) {
            int idx = tid + i*256;
            int r = idx >> 4, c4 = (idx & 15) << 2;
            float4 v = *(const float4*)(W + (size_t)(nt*64 + r)*64 + c4);
            *(float4*)(&Bs[ASWI(r, c4)]) = v;
        }
        __syncthreads();

        float c[2][4][4];
        #pragma unroll
        for (int i = 0; i < 2; i++)
            #pragma unroll
            for (int j = 0; j < 4; j++)
                #pragma unroll
                for (int r = 0; r < 4; r++) c[i][j][r] = 0.f;

        #pragma unroll
        for (int kc = 0; kc < 8; kc++) {
            int kb = kc*8;
            unsigned a[2][4], b[4][2];
            #pragma unroll
            for (int i = 0; i < 2; i++) {
                int r = wm*32 + i*16 + qr;
                a[i][0] = As[ASWI(r,     kb + qk)];
                a[i][1] = As[ASWI(r + 8, kb + qk)];
                a[i][2] = As[ASWI(r,     kb + qk + 4)];
                a[i][3] = As[ASWI(r + 8, kb + qk + 4)];
            }
            #pragma unroll
            for (int j = 0; j < 4; j++) {
                int nn = wn*32 + j*8 + qr;
                b[j][0] = Bs[ASWI(nn, kb + qk)];
                b[j][1] = Bs[ASWI(nn, kb + qk + 4)];
            }
            #pragma unroll
            for (int i = 0; i < 2; i++)
                #pragma unroll
                for (int j = 0; j < 4; j++)
                    mma_tf32(c[i][j][0], c[i][j][1], c[i][j][2], c[i][j][3],
                             a[i][0], a[i][1], a[i][2], a[i][3], b[j][0], b[j][1]);
        }

        #pragma unroll
        for (int i = 0; i < 2; i++) {
            #pragma unroll
            for (int half = 0; half < 2; half++) {
                int gr = row0 + wm*32 + i*16 + qr + half*8;
                if (gr >= MROWS) continue;
                #pragma unroll
                for (int j = 0; j < 4; j++) {
                    int gc = nt*64 + wn*32 + j*8 + qk*2;
                    float v0 = c[i][j][half*2]     + bias[gc];
                    float v1 = c[i][j][half*2 + 1] + bias[gc + 1];
                    *(float2*)(out + (size_t)gr*192 + gc) = make_float2(v0, v1);
                }
            }
        }
    }
}

// ---------------- fused layer kernel -----------------------------------------
// 512 threads, 128 rows/block. out-proj + residual + LN2 + FF + residual
// + (optional) LN1next + QKVnext. Dynamic smem 113KB, 2 CTAs/SM.
#define LSM_A 0
#define LSM_Z 32768
#define LSM_W 65536
#define LSM_H 81920
#define LSM_TOTAL 115712   // 81920 + 128*66*4

__global__ void __launch_bounds__(512, 2)
layer_kernel(const float* __restrict__ o,
             const float* __restrict__ Wout, const float* __restrict__ bout,
             float* __restrict__ h,
             const float* __restrict__ ln2g, const float* __restrict__ ln2b,
             const float* __restrict__ W1, const float* __restrict__ b1,
             const float* __restrict__ W2, const float* __restrict__ b2,
             const float* __restrict__ ln1g, const float* __restrict__ ln1b,
             const float* __restrict__ Wq, const float* __restrict__ bq,
             float* __restrict__ qkvout) {
    extern __shared__ __align__(16) char sm[];
    unsigned* Abuf = (unsigned*)(sm + LSM_A);   // 128x64
    unsigned* Zbuf = (unsigned*)(sm + LSM_Z);   // 128x64
    unsigned* Wbuf = (unsigned*)(sm + LSM_W);   // 64x64
    float*    Hbuf = (float*)(sm + LSM_H);      // 128 x stride 66

    int tid = threadIdx.x;
    int warp = tid >> 5, lane = tid & 31;
    int wm = warp >> 1, wn = warp & 1;          // 8 x 2
    int row0 = blockIdx.x * 128;
    int qr = lane >> 2, qk = lane & 3;
    int rlo = wm*16 + qr, rhi = rlo + 8;
    int grlo = row0 + rlo, grhi = row0 + rhi;

    // ---- stage o (128x64) + Wout (64x64) ----
    #pragma unroll
    for (int i = 0; i < 4; i++) {
        int idx = tid + i*512;
        int r = idx >> 4, c4 = (idx & 15) << 2;
        int gr = row0 + r;
        float4 v = (gr < MROWS) ? *(const float4*)(o + (size_t)gr*64 + c4)
                                : make_float4(0.f,0.f,0.f,0.f);
        *(float4*)(&Abuf[ASWI(r, c4)]) = v;
    }
    #pragma unroll
    for (int i = 0; i < 2; i++) {
        int idx = tid + i*512;
        int r = idx >> 4, c4 = (idx & 15) << 2;
        float4 w = *(const float4*)(Wout + (size_t)r*64 + c4);
        *(float4*)(&Wbuf[ASWI(r, c4)]) = w;
    }
    __syncthreads();

    // ---- out-proj mma ----
    {
        float c[4][4];
        #pragma unroll
        for (int j = 0; j < 4; j++)
            #pragma unroll
            for (int r = 0; r < 4; r++) c[j][r] = 0.f;
        #pragma unroll
        for (int kc = 0; kc < 8; kc++) {
            int kb = kc*8;
            unsigned a0 = Abuf[ASWI(rlo, kb + qk)];
            unsigned a1 = Abuf[ASWI(rhi, kb + qk)];
            unsigned a2 = Abuf[ASWI(rlo, kb + qk + 4)];
            unsigned a3 = Abuf[ASWI(rhi, kb + qk + 4)];
            #pragma unroll
            for (int j = 0; j < 4; j++) {
                int nn = wn*32 + j*8 + qr;
                mma_tf32(c[j][0], c[j][1], c[j][2], c[j][3],
                         a0, a1, a2, a3,
                         Wbuf[ASWI(nn, kb + qk)], Wbuf[ASWI(nn, kb + qk + 4)]);
            }
        }
        // residual h' -> Hbuf
        #pragma unroll
        for (int j = 0; j < 4; j++) {
            int gc = wn*32 + j*8 + 2*qk;
            float hv0 = c[j][0] + bout[gc], hv1 = c[j][1] + bout[gc+1];
            float hv2 = c[j][2] + bout[gc], hv3 = c[j][3] + bout[gc+1];
            if (grlo < MROWS) { float2 t = *(const float2*)(h + (size_t)grlo*64 + gc); hv0 += t.x; hv1 += t.y; }
            if (grhi < MROWS) { float2 t = *(const float2*)(h + (size_t)grhi*64 + gc); hv2 += t.x; hv3 += t.y; }
            *(float2*)(&Hbuf[rlo*66 + gc]) = make_float2(hv0, hv1);
            *(float2*)(&Hbuf[rhi*66 + gc]) = make_float2(hv2, hv3);
        }
    }
    __syncthreads();

    // ---- LN2 -> y2 into Abuf ----
    for (int rr = warp; rr < 128; rr += 16) {
        float2 v = *(float2*)(&Hbuf[rr*66 + 2*lane]);
        float mu = warp_sum(v.x + v.y) * (1.0f/64.0f);
        float a0 = v.x - mu, a1 = v.y - mu;
        float var = warp_sum(a0*a0 + a1*a1) * (1.0f/64.0f);
        float rs = rsqrtf(var + EPS);
        float2 gg = ((const float2*)ln2g)[lane];
        float2 bb = ((const float2*)ln2b)[lane];
        *(float2*)(&Abuf[ASWI(rr, 2*lane)]) =
            make_float2(a0*rs*gg.x + bb.x, a1*rs*gg.y + bb.y);
    }
    __syncthreads();

    // ---- FF: z stays in smem ----
    float d[4][4];
    #pragma unroll
    for (int j = 0; j < 4; j++)
        #pragma unroll
        for (int r = 0; r < 4; r++) d[j][r] = 0.f;

    for (int t = 0; t < 4; t++) {
        #pragma unroll
        for (int i = 0; i < 2; i++) {
            int idx = tid + i*512;
            int r = idx >> 4, c4 = (idx & 15) << 2;
            float4 w = *(const float4*)(W1 + (size_t)(t*64 + r)*64 + c4);
            *(float4*)(&Wbuf[ASWI(r, c4)]) = w;
        }
        __syncthreads();

        float zc[4][4];
        #pragma unroll
        for (int j = 0; j < 4; j++)
            #pragma unroll
            for (int r = 0; r < 4; r++) zc[j][r] = 0.f;
        #pragma unroll
        for (int kc = 0; kc < 8; kc++) {
            int kb = kc*8;
            unsigned a0 = Abuf[ASWI(rlo, kb + qk)];
            unsigned a1 = Abuf[ASWI(rhi, kb + qk)];
            unsigned a2 = Abuf[ASWI(rlo, kb + qk + 4)];
            unsigned a3 = Abuf[ASWI(rhi, kb + qk + 4)];
            #pragma unroll
            for (int j = 0; j < 4; j++) {
                int nn = wn*32 + j*8 + qr;
                mma_tf32(zc[j][0], zc[j][1], zc[j][2], zc[j][3],
                         a0, a1, a2, a3,
                         Wbuf[ASWI(nn, kb + qk)], Wbuf[ASWI(nn, kb + qk + 4)]);
            }
        }
        #pragma unroll
        for (int j = 0; j < 4; j++) {
            int lc = wn*32 + j*8 + 2*qk;
            int gc = t*64 + lc;
            float z0 = gelu_exact(zc[j][0] + b1[gc]);
            float z1 = gelu_exact(zc[j][1] + b1[gc+1]);
            float z2 = gelu_exact(zc[j][2] + b1[gc]);
            float z3 = gelu_exact(zc[j][3] + b1[gc+1]);
            *(float2*)(&Zbuf[ASWI(rlo, lc)]) = make_float2(z0, z1);
            *(float2*)(&Zbuf[ASWI(rhi, lc)]) = make_float2(z2, z3);
        }
        __syncthreads();

        #pragma unroll
        for (int i = 0; i < 2; i++) {
            int idx = tid + i*512;
            int r = idx >> 4, c4 = (idx & 15) << 2;
            float4 w = *(const float4*)(W2 + (size_t)r*256 + t*64 + c4);
            *(float4*)(&Wbuf[ASWI(r, c4)]) = w;
        }
        __syncthreads();

        #pragma unroll
        for (int kc = 0; kc < 8; kc++) {
            int kb = kc*8;
            unsigned a0 = Zbuf[ASWI(rlo, kb + qk)];
            unsigned a1 = Zbuf[ASWI(rhi, kb + qk)];
            unsigned a2 = Zbuf[ASWI(rlo, kb + qk + 4)];
            unsigned a3 = Zbuf[ASWI(rhi, kb + qk + 4)];
            #pragma unroll
            for (int j = 0; j < 4; j++) {
                int nn = wn*32 + j*8 + qr;
                mma_tf32(d[j][0], d[j][1], d[j][2], d[j][3],
                         a0, a1, a2, a3,
                         Wbuf[ASWI(nn, kb + qk)], Wbuf[ASWI(nn, kb + qk + 4)]);
            }
        }
        __syncthreads();
    }

    // ---- epilogue: hn = h' + ff2out; write h; keep in Hbuf ----
    #pragma unroll
    for (int j = 0; j < 4; j++) {
        int gc = wn*32 + j*8 + 2*qk;
        float2 hlo = *(float2*)(&Hbuf[rlo*66 + gc]);
        float2 hhi = *(float2*)(&Hbuf[rhi*66 + gc]);
        float v0 = d[j][0] + b2[gc]   + hlo.x;
        float v1 = d[j][1] + b2[gc+1] + hlo.y;
        float v2 = d[j][2] + b2[gc]   + hhi.x;
        float v3 = d[j][3] + b2[gc+1] + hhi.y;
        if (grlo < MROWS) *(float2*)(h + (size_t)grlo*64 + gc) = make_float2(v0, v1);
        if (grhi < MROWS) *(float2*)(h + (size_t)grhi*64 + gc) = make_float2(v2, v3);
        *(float2*)(&Hbuf[rlo*66 + gc]) = make_float2(v0, v1);
        *(float2*)(&Hbuf[rhi*66 + gc]) = make_float2(v2, v3);
    }

    if (ln1g == nullptr) return;
    __syncthreads();

    // ---- LN1next -> Abuf ----
    for (int rr = warp; rr < 128; rr += 16) {
        float2 v = *(float2*)(&Hbuf[rr*66 + 2*lane]);
        float mu = warp_sum(v.x + v.y) * (1.0f/64.0f);
        float a0 = v.x - mu, a1 = v.y - mu;
        float var = warp_sum(a0*a0 + a1*a1) * (1.0f/64.0f);
        float rs = rsqrtf(var + EPS);
        float2 gg = ((const float2*)ln1g)[lane];
        float2 bb = ((const float2*)ln1b)[lane];
        *(float2*)(&Abuf[ASWI(rr, 2*lane)]) =
            make_float2(a0*rs*gg.x + bb.x, a1*rs*gg.y + bb.y);
    }

    // ---- QKV next layer ----
    for (int nt = 0; nt < 3; nt++) {
        __syncthreads();
        #pragma unroll
        for (int i = 0; i < 2; i++) {
            int idx = tid + i*512;
            int r = idx >> 4, c4 = (idx & 15) << 2;
            float4 w = *(const float4*)(Wq + (size_t)(nt*64 + r)*64 + c4);
            *(float4*)(&Wbuf[ASWI(r, c4)]) = w;
        }
        __syncthreads();

        float c[4][4];
        #pragma unroll
        for (int j = 0; j < 4; j++)
            #pragma unroll
            for (int r = 0; r < 4; r++) c[j][r] = 0.f;
        #pragma unroll
        for (int kc = 0; kc < 8; kc++) {
            int kb = kc*8;
            unsigned a0 = Abuf[ASWI(rlo, kb + qk)];
            unsigned a1 = Abuf[ASWI(rhi, kb + qk)];
            unsigned a2 = Abuf[ASWI(rlo, kb + qk + 4)];
            unsigned a3 = Abuf[ASWI(rhi, kb + qk + 4)];
            #pragma unroll
            for (int j = 0; j < 4; j++) {
                int nn = wn*32 + j*8 + qr;
                mma_tf32(c[j][0], c[j][1], c[j][2], c[j][3],
                         a0, a1, a2, a3,
                         Wbuf[ASWI(nn, kb + qk)], Wbuf[ASWI(nn, kb + qk + 4)]);
            }
        }
        #pragma unroll
        for (int j = 0; j < 4; j++) {
            int gc = nt*64 + wn*32 + j*8 + 2*qk;
            float v0 = c[j][0] + bq[gc];
            float v1 = c[j][1] + bq[gc+1];
            float v2 = c[j][2] + bq[gc];
            float v3 = c[j][3] + bq[gc+1];
            if (grlo < MROWS) *(float2*)(qkvout + (size_t)grlo*192 + gc) = make_float2(v0, v1);
            if (grhi < MROWS) *(float2*)(qkvout + (size_t)grhi*192 + gc) = make_float2(v2, v3);
        }
    }
}

// ---------------- tensor-core flash attention --------------------------------
#define KSTR 12
#define VSTR 308

__global__ void __launch_bounds__(320) attn_kernel(const float* __restrict__ qkv,
                                                   float* __restrict__ o) {
    __shared__ unsigned Ks[304*KSTR];
    __shared__ unsigned Vt[8*VSTR];
    int n = blockIdx.x >> 3;
    int h = blockIdx.x & 7;
    int tid = threadIdx.x, warp = tid >> 5, lane = tid & 31;
    int gr = lane >> 2, t4 = lane & 3;
    const float* base = qkv + (size_t)n*SS*(3*DD) + h*HD;

    for (int i = tid; i < 304*8; i += 320) {
        int s = i >> 3, d = i & 7;
        float kv = 0.f, vv = 0.f;
        if (s < SS) {
            const float* rp = base + (size_t)s*(3*DD);
            kv = rp[DD + d];
            vv = rp[2*DD + d];
        }
        Ks[s*KSTR + d] = __float_as_uint(kv);
        Vt[d*VSTR + s] = __float_as_uint(vv);
    }
    __syncthreads();

    const float sc = 0.35355339059327373f * 1.4426950408889634f;

    for (int tile = warp; tile < 19; tile += 10) {
        int q0 = tile*16;
        int r0 = min(q0 + gr, SS-1);
        int r1 = min(q0 + gr + 8, SS-1);
        const float* qp0 = base + (size_t)r0*(3*DD);
        const float* qp1 = base + (size_t)r1*(3*DD);
        unsigned qa0 = __float_as_uint(qp0[t4]*sc);
        unsigned qa1 = __float_as_uint(qp1[t4]*sc);
        unsigned qa2 = __float_as_uint(qp0[t4+4]*sc);
        unsigned qa3 = __float_as_uint(qp1[t4+4]*sc);

        float o0=0.f, o1=0.f, o2=0.f, o3=0.f;
        float l0=0.f, l1=0.f;

        #pragma unroll 2
        for (int kt = 0; kt < 38; kt++) {
            int kb = kt*8;
            unsigned b0 = Ks[(kb + gr)*KSTR + t4];
            unsigned b1 = Ks[(kb + gr)*KSTR + t4 + 4];
            float c0=0.f, c1=0.f, c2=0.f, c3=0.f;
            mma_tf32(c0, c1, c2, c3, qa0, qa1, qa2, qa3, b0, b1);

            float p0, p1, p2, p3;
            asm("ex2.approx.f32 %0, %1;" : "=f"(p0) : "f"(c0));
            asm("ex2.approx.f32 %0, %1;" : "=f"(p1) : "f"(c1));
            asm("ex2.approx.f32 %0, %1;" : "=f"(p2) : "f"(c2));
            asm("ex2.approx.f32 %0, %1;" : "=f"(p3) : "f"(c3));
            if (kt == 37) {
                if (kb + 2*t4     > 300) { p0 = 0.f; p2 = 0.f; }
                if (kb + 2*t4 + 1 > 300) { p1 = 0.f; p3 = 0.f; }
            }
            l0 += p0 + p1;
            l1 += p2 + p3;

            int srcA = (lane & 0x1c) | (t4 >> 1);
            int srcB = srcA + 2;
            float s0 = __shfl_sync(0xffffffffu, p0, srcA);
            float s1 = __shfl_sync(0xffffffffu, p1, srcA);
            float s2 = __shfl_sync(0xffffffffu, p2, srcA);
            float s3 = __shfl_sync(0xffffffffu, p3, srcA);
            float s4 = __shfl_sync(0xffffffffu, p0, srcB);
            float s5 = __shfl_sync(0xffffffffu, p1, srcB);
            float s6 = __shfl_sync(0xffffffffu, p2, srcB);
            float s7 = __shfl_sync(0xffffffffu, p3, srcB);
            bool oddc = (t4 & 1);
            unsigned pa0 = __float_as_uint(oddc ? s1 : s0);
            unsigned pa1 = __float_as_uint(oddc ? s3 : s2);
            unsigned pa2 = __float_as_uint(oddc ? s5 : s4);
            unsigned pa3 = __float_as_uint(oddc ? s7 : s6);

            unsigned vb0 = Vt[gr*VSTR + kb + t4];
            unsigned vb1 = Vt[gr*VSTR + kb + t4 + 4];
            mma_tf32(o0, o1, o2, o3, pa0, pa1, pa2, pa3, vb0, vb1);
        }

        l0 += __shfl_xor_sync(0xffffffffu, l0, 1);
        l0 += __shfl_xor_sync(0xffffffffu, l0, 2);
        l1 += __shfl_xor_sync(0xffffffffu, l1, 1);
        l1 += __shfl_xor_sync(0xffffffffu, l1, 2);
        float inv0 = 1.0f / l0, inv1 = 1.0f / l1;

        int row0g = q0 + gr, row1g = q0 + gr + 8;
        if (row0g < SS)
            *(float2*)(o + ((size_t)n*SS + row0g)*DD + h*HD + 2*t4) =
                make_float2(o0*inv0, o1*inv0);
        if (row1g < SS)
            *(float2*)(o + ((size_t)n*SS + row1g)*DD + h*HD + 2*t4) =
                make_float2(o2*inv1, o3*inv1);
    }
}

// ---------------- cls pool over edges + LayerNorm ----------------------------
__global__ void pool_kernel(const float* __restrict__ g, const float* __restrict__ bt) {
    int warp = threadIdx.x >> 5;
    int lane = threadIdx.x & 31;
    if (warp >= BB) return;
    int b = warp;
    float v0 = 0.f, v1 = 0.f;
    for (int e = 0; e < EE; e++) {
        size_t base = ((size_t)(b*EE + e)*SS)*DD;
        v0 += g_h[base + lane];
        v1 += g_h[base + lane + 32];
    }
    v0 *= (1.0f/EE); v1 *= (1.0f/EE);
    float mu = warp_sum(v0 + v1) * (1.0f/64.0f);
    float a0 = v0 - mu, a1 = v1 - mu;
    float var = warp_sum(a0*a0 + a1*a1) * (1.0f/64.0f);
    float rs = rsqrtf(var + EPS);
    g_feat[b*DD + lane]    = a0*rs*g[lane]    + bt[lane];
    g_feat[b*DD + lane+32] = a1*rs*g[lane+32] + bt[lane+32];
}

// ---------------- head MLP ---------------------------------------------------
__global__ void head1_kernel(const float* __restrict__ w, const float* __restrict__ bias) {
    __shared__ float f[DD];
    int b = blockIdx.x, d = threadIdx.x;
    f[d] = g_feat[b*DD + d];
    __syncthreads();
    float acc = bias[d];
    #pragma unroll 8
    for (int k = 0; k < DD; k++) acc = fmaf(f[k], w[d*DD + k], acc);
    g_feat2[b*DD + d] = gelu_exact(acc);
}

__global__ void head2_kernel(const float* __restrict__ w, const float* __restrict__ bias,
                             float* __restrict__ out) {
    __shared__ float f[DD];
    int b = blockIdx.x, c = threadIdx.x;
    f[c] = g_feat2[b*DD + c];
    __syncthreads();
    if (c >= NCLS) return;
    float acc = bias[c];
    #pragma unroll 8
    for (int k = 0; k < DD; k++) acc = fmaf(f[k], w[c*DD + k], acc);
    out[b*NCLS + c] = acc;
}

// ---------------- launcher ---------------------------------------------------
extern "C" void kernel_launch(void* const* d_in, const int* in_sizes, int n_in,
                              void* d_out, int out_size) {
    const float* x       = (const float*)d_in[0];
    const float* embed_w = (const float*)d_in[1];
    const float* embed_b = (const float*)d_in[2];
    const float* eln_g   = (const float*)d_in[3];
    const float* eln_b   = (const float*)d_in[4];
    const float* cls     = (const float*)d_in[5];
    const float* qkv_w   = (const float*)d_in[6];
    const float* qkv_b   = (const float*)d_in[7];
    const float* out_w   = (const float*)d_in[8];
    const float* out_b   = (const float*)d_in[9];
    const float* ln1_g   = (const float*)d_in[10];
    const float* ln1_b   = (const float*)d_in[11];
    const float* ln2_g   = (const float*)d_in[12];
    const float* ln2_b   = (const float*)d_in[13];
    const float* ff1_w   = (const float*)d_in[14];
    const float* ff1_b   = (const float*)d_in[15];
    const float* ff2_w   = (const float*)d_in[16];
    const float* ff2_b   = (const float*)d_in[17];
    const float* norm_g  = (const float*)d_in[18];
    const float* norm_b  = (const float*)d_in[19];
    const float* h1_w    = (const float*)d_in[20];
    const float* h1_b    = (const float*)d_in[21];
    const float* h2_w    = (const float*)d_in[22];
    const float* h2_b    = (const float*)d_in[23];
    float* out = (float*)d_out;

    float *hbuf, *ybuf, *qkvbuf, *obuf;
    cudaGetSymbolAddress((void**)&hbuf,   g_h);
    cudaGetSymbolAddress((void**)&ybuf,   g_y);
    cudaGetSymbolAddress((void**)&qkvbuf, g_qkv);
    cudaGetSymbolAddress((void**)&obuf,   g_o);

    cudaFuncSetAttribute(layer_kernel,
                         cudaFuncAttributeMaxDynamicSharedMemorySize, LSM_TOTAL);

    const int rows_grid = (MROWS + 7) / 8;
    const int gm128 = (MROWS + 127) / 128;  // 941

    embed_kernel<<<rows_grid, 256>>>(x, embed_w, embed_b, eln_g, eln_b, cls,
                                     ln1_g, ln1_b);
    qkv_gemm<<<gm128, 256>>>(ybuf, qkv_w, qkv_b, qkvbuf);

    for (int l = 0; l < LL; l++) {
        attn_kernel<<<NN*HH, 320>>>(qkvbuf, obuf);
        bool last = (l == LL-1);
        const float* nlg = last ? nullptr : (ln1_g + (l+1)*DD);
        const float* nlb = last ? nullptr : (ln1_b + (l+1)*DD);
        const float* nWq = last ? nullptr : (qkv_w + (size_t)(l+1)*3*DD*DD);
        const float* nbq = last ? nullptr : (qkv_b + (l+1)*3*DD);
        layer_kernel<<<gm128, 512, LSM_TOTAL>>>(
            obuf, out_w + (size_t)l*DD*DD, out_b + l*DD,
            hbuf, ln2_g + l*DD, ln2_b + l*DD,
            ff1_w + (size_t)l*FFD*DD, ff1_b + l*FFD,
            ff2_w + (size_t)l*DD*FFD, ff2_b + l*DD,
            nlg, nlb, nWq, nbq, qkvbuf);
    }

    pool_kernel<<<1, 512>>>(norm_g, norm_b);
    head1_kernel<<<BB, DD>>>(h1_w, h1_b);
    head2_kernel<<<BB, DD>>>(h2_w, h2_b, out);
}

// round 10
// speedup vs baseline: 1.0928x; 1.0928x over previous
#include <cuda_runtime.h>
#include <cuda_bf16.h>
#include <math.h>

// Problem constants
#define BB 16
#define EE 25
#define TT 300
#define CC 3
#define DD 64
#define HH 8
#define FFD 256
#define LL 4
#define NCLS 60
#define NN (BB*EE)        // 400
#define SS (TT+1)         // 301
#define HD (DD/HH)        // 8
#define MROWS (NN*SS)     // 120400
#define EPS 1e-5f

// ---------------- scratch buffers -------------------------------------------
__device__ float g_h[MROWS*DD];      // residual stream
__device__ float g_y[MROWS*DD];      // LN output
__device__ float g_qkv[MROWS*3*DD];  // qkv
__device__ float g_o[MROWS*DD];      // attention output
__device__ float g_feat[BB*DD];
__device__ float g_feat2[BB*DD];

// ---------------- helpers ---------------------------------------------------
__device__ __forceinline__ float warp_sum(float v) {
    #pragma unroll
    for (int o = 16; o; o >>= 1) v += __shfl_xor_sync(0xffffffffu, v, o);
    return v;
}

__device__ __forceinline__ float gelu_exact(float x) {
    return 0.5f * x * (1.0f + erff(x * 0.70710678118654752f));
}

__device__ __forceinline__ void mma_tf32(float& c0, float& c1, float& c2, float& c3,
                                         unsigned a0, unsigned a1, unsigned a2, unsigned a3,
                                         unsigned b0, unsigned b1) {
    asm volatile(
        "mma.sync.aligned.m16n8k8.row.col.f32.tf32.tf32.f32 "
        "{%0,%1,%2,%3}, {%4,%5,%6,%7}, {%8,%9}, {%0,%1,%2,%3};"
        : "+f"(c0), "+f"(c1), "+f"(c2), "+f"(c3)
        : "r"(a0), "r"(a1), "r"(a2), "r"(a3), "r"(b0), "r"(b1));
}

#define ASWI(r,c) ((r)*64 + (((c) ^ (((r)&7)<<2))))

// ---------------- embed + LN + cls + pos + fused ln1[0] ----------------------
__global__ void embed_kernel(const float* __restrict__ x,
                             const float* __restrict__ ew,
                             const float* __restrict__ ebias,
                             const float* __restrict__ eg,
                             const float* __restrict__ ebt,
                             const float* __restrict__ cls,
                             const float* __restrict__ l1g,
                             const float* __restrict__ l1b) {
    int warp = (blockIdx.x * blockDim.x + threadIdx.x) >> 5;
    int lane = threadIdx.x & 31;
    if (warp >= MROWS) return;
    int n = warp / SS, s = warp % SS;
    int b = n / EE, e = n % EE;

    float v0, v1;
    if (s == 0) {
        v0 = cls[lane];
        v1 = cls[lane + 32];
    } else {
        int t = s - 1;
        float x0 = x[((b*CC + 0)*TT + t)*EE + e];
        float x1 = x[((b*CC + 1)*TT + t)*EE + e];
        float x2 = x[((b*CC + 2)*TT + t)*EE + e];
        int d0 = lane, d1 = lane + 32;
        v0 = ebias[d0] + x0*ew[d0*3] + x1*ew[d0*3+1] + x2*ew[d0*3+2];
        v1 = ebias[d1] + x0*ew[d1*3] + x1*ew[d1*3+1] + x2*ew[d1*3+2];
        float mu = warp_sum(v0 + v1) * (1.0f/64.0f);
        float a0 = v0 - mu, a1 = v1 - mu;
        float var = warp_sum(a0*a0 + a1*a1) * (1.0f/64.0f);
        float r = rsqrtf(var + EPS);
        v0 = a0 * r * eg[d0] + ebt[d0];
        v1 = a1 * r * eg[d1] + ebt[d1];
    }
    const float kfreq = -0.14391565f; // -ln(10000)/64
    {
        int d0 = lane;
        int i = d0 >> 1;
        float ang = (float)s * __expf((float)(2*i) * kfreq);
        v0 += (d0 & 1) ? cosf(ang) : sinf(ang);
        int d1 = lane + 32;
        i = d1 >> 1;
        ang = (float)s * __expf((float)(2*i) * kfreq);
        v1 += (d1 & 1) ? cosf(ang) : sinf(ang);
    }
    g_h[warp*DD + lane]      = v0;
    g_h[warp*DD + lane + 32] = v1;
    // fused ln1[0]
    float mu = warp_sum(v0 + v1) * (1.0f/64.0f);
    float a0 = v0 - mu, a1 = v1 - mu;
    float var = warp_sum(a0*a0 + a1*a1) * (1.0f/64.0f);
    float rs = rsqrtf(var + EPS);
    g_y[warp*DD + lane]      = a0*rs*l1g[lane]    + l1b[lane];
    g_y[warp*DD + lane + 32] = a1*rs*l1g[lane+32] + l1b[lane+32];
}

// ---------------- qkv GEMM ----------------------------------------------------
__global__ void __launch_bounds__(256, 2)
qkv_gemm(const float* __restrict__ A, const float* __restrict__ W,
         const float* __restrict__ bias, float* __restrict__ out) {
    __shared__ unsigned As[128*64];
    __shared__ unsigned Bs[64*64];
    int tid = threadIdx.x;
    int warp = tid >> 5, lane = tid & 31;
    int wm = warp >> 1, wn = warp & 1;
    int row0 = blockIdx.x * 128;
    int qr = lane >> 2, qk = lane & 3;

    #pragma unroll
    for (int i = 0; i < 8; i++) {
        int idx = tid + i*256;
        int r = idx >> 4, c4 = (idx & 15) << 2;
        int gr = row0 + r;
        float4 v = (gr < MROWS) ? *(const float4*)(A + (size_t)gr*64 + c4)
                                : make_float4(0.f,0.f,0.f,0.f);
        *(float4*)(&As[ASWI(r, c4)]) = v;
    }

    for (int nt = 0; nt < 3; nt++) {
        if (nt) __syncthreads();
        #pragma unroll
        for (int i = 0; i < 4; i++) {
            int idx = tid + i*256;
            int r = idx >> 4, c4 = (idx & 15) << 2;
            float4 v = *(const float4*)(W + (size_t)(nt*64 + r)*64 + c4);
            *(float4*)(&Bs[ASWI(r, c4)]) = v;
        }
        __syncthreads();

        float c[2][4][4];
        #pragma unroll
        for (int i = 0; i < 2; i++)
            #pragma unroll
            for (int j = 0; j < 4; j++)
                #pragma unroll
                for (int r = 0; r < 4; r++) c[i][j][r] = 0.f;

        #pragma unroll
        for (int kc = 0; kc < 8; kc++) {
            int kb = kc*8;
            unsigned a[2][4], b[4][2];
            #pragma unroll
            for (int i = 0; i < 2; i++) {
                int r = wm*32 + i*16 + qr;
                a[i][0] = As[ASWI(r,     kb + qk)];
                a[i][1] = As[ASWI(r + 8, kb + qk)];
                a[i][2] = As[ASWI(r,     kb + qk + 4)];
                a[i][3] = As[ASWI(r + 8, kb + qk + 4)];
            }
            #pragma unroll
            for (int j = 0; j < 4; j++) {
                int nn = wn*32 + j*8 + qr;
                b[j][0] = Bs[ASWI(nn, kb + qk)];
                b[j][1] = Bs[ASWI(nn, kb + qk + 4)];
            }
            #pragma unroll
            for (int i = 0; i < 2; i++)
                #pragma unroll
                for (int j = 0; j < 4; j++)
                    mma_tf32(c[i][j][0], c[i][j][1], c[i][j][2], c[i][j][3],
                             a[i][0], a[i][1], a[i][2], a[i][3], b[j][0], b[j][1]);
        }

        #pragma unroll
        for (int i = 0; i < 2; i++) {
            #pragma unroll
            for (int half = 0; half < 2; half++) {
                int gr = row0 + wm*32 + i*16 + qr + half*8;
                if (gr >= MROWS) continue;
                #pragma unroll
                for (int j = 0; j < 4; j++) {
                    int gc = nt*64 + wn*32 + j*8 + qk*2;
                    float v0 = c[i][j][half*2]     + bias[gc];
                    float v1 = c[i][j][half*2 + 1] + bias[gc + 1];
                    *(float2*)(out + (size_t)gr*192 + gc) = make_float2(v0, v1);
                }
            }
        }
    }
}

// ---------------- fused half layer (dynamic smem, 3 CTAs/SM) -----------------
#define HSM_A 0
#define HSM_Z 16384
#define HSM_W 32768
#define HSM_H 49152
#define HSM_TOTAL 66048   // 49152 + 64*66*4

__global__ void __launch_bounds__(256, 3)
half_layer(const float* __restrict__ o,
           const float* __restrict__ Wout, const float* __restrict__ bout,
           float* __restrict__ h,
           const float* __restrict__ ln2g, const float* __restrict__ ln2b,
           const float* __restrict__ W1, const float* __restrict__ b1,
           const float* __restrict__ W2, const float* __restrict__ b2,
           const float* __restrict__ ln1g, const float* __restrict__ ln1b,
           float* __restrict__ y) {
    extern __shared__ __align__(16) char sm[];
    unsigned* Abuf = (unsigned*)(sm + HSM_A);   // 64x64
    unsigned* Zbuf = (unsigned*)(sm + HSM_Z);   // 64x64
    unsigned* Wbuf = (unsigned*)(sm + HSM_W);   // 64x64
    float*    Hbuf = (float*)(sm + HSM_H);      // 64 x stride 66

    int tid = threadIdx.x;
    int warp = tid >> 5, lane = tid & 31;
    int wm = warp >> 1, wn = warp & 1;
    int row0 = blockIdx.x * 64;
    int qr = lane >> 2, qk = lane & 3;
    int rlo = wm*16 + qr, rhi = rlo + 8;
    int grlo = row0 + rlo, grhi = row0 + rhi;

    // ---- stage o + Wout ----
    #pragma unroll
    for (int i = 0; i < 4; i++) {
        int idx = tid + i*256;
        int r = idx >> 4, c4 = (idx & 15) << 2;
        int gr = row0 + r;
        float4 v = (gr < MROWS) ? *(const float4*)(o + (size_t)gr*64 + c4)
                                : make_float4(0.f,0.f,0.f,0.f);
        *(float4*)(&Abuf[ASWI(r, c4)]) = v;
        float4 w = *(const float4*)(Wout + (size_t)r*64 + c4);
        *(float4*)(&Wbuf[ASWI(r, c4)]) = w;
    }
    __syncthreads();

    // ---- out-proj mma -> residual into Hbuf ----
    {
        float c[4][4];
        #pragma unroll
        for (int j = 0; j < 4; j++)
            #pragma unroll
            for (int r = 0; r < 4; r++) c[j][r] = 0.f;
        #pragma unroll
        for (int kc = 0; kc < 8; kc++) {
            int kb = kc*8;
            unsigned a0 = Abuf[ASWI(rlo, kb + qk)];
            unsigned a1 = Abuf[ASWI(rhi, kb + qk)];
            unsigned a2 = Abuf[ASWI(rlo, kb + qk + 4)];
            unsigned a3 = Abuf[ASWI(rhi, kb + qk + 4)];
            #pragma unroll
            for (int j = 0; j < 4; j++) {
                int nn = wn*32 + j*8 + qr;
                mma_tf32(c[j][0], c[j][1], c[j][2], c[j][3],
                         a0, a1, a2, a3,
                         Wbuf[ASWI(nn, kb + qk)], Wbuf[ASWI(nn, kb + qk + 4)]);
            }
        }
        #pragma unroll
        for (int j = 0; j < 4; j++) {
            int gc = wn*32 + j*8 + 2*qk;
            float hv0 = c[j][0] + bout[gc], hv1 = c[j][1] + bout[gc+1];
            float hv2 = c[j][2] + bout[gc], hv3 = c[j][3] + bout[gc+1];
            if (grlo < MROWS) { float2 t = *(const float2*)(h + (size_t)grlo*64 + gc); hv0 += t.x; hv1 += t.y; }
            if (grhi < MROWS) { float2 t = *(const float2*)(h + (size_t)grhi*64 + gc); hv2 += t.x; hv3 += t.y; }
            *(float2*)(&Hbuf[rlo*66 + gc]) = make_float2(hv0, hv1);
            *(float2*)(&Hbuf[rhi*66 + gc]) = make_float2(hv2, hv3);
        }
    }
    __syncthreads();

    // ---- LN2 -> y2 into Abuf ----
    for (int rr = warp; rr < 64; rr += 8) {
        float2 v = *(float2*)(&Hbuf[rr*66 + 2*lane]);
        float mu = warp_sum(v.x + v.y) * (1.0f/64.0f);
        float a0 = v.x - mu, a1 = v.y - mu;
        float var = warp_sum(a0*a0 + a1*a1) * (1.0f/64.0f);
        float rs = rsqrtf(var + EPS);
        float2 gg = ((const float2*)ln2g)[lane];
        float2 bb = ((const float2*)ln2b)[lane];
        *(float2*)(&Abuf[ASWI(rr, 2*lane)]) =
            make_float2(a0*rs*gg.x + bb.x, a1*rs*gg.y + bb.y);
    }
    __syncthreads();

    // ---- FF: z stays in smem ----
    float d[4][4];
    #pragma unroll
    for (int j = 0; j < 4; j++)
        #pragma unroll
        for (int r = 0; r < 4; r++) d[j][r] = 0.f;

    for (int t = 0; t < 4; t++) {
        #pragma unroll
        for (int i = 0; i < 4; i++) {
            int idx = tid + i*256;
            int r = idx >> 4, c4 = (idx & 15) << 2;
            float4 w = *(const float4*)(W1 + (size_t)(t*64 + r)*64 + c4);
            *(float4*)(&Wbuf[ASWI(r, c4)]) = w;
        }
        __syncthreads();

        float zc[4][4];
        #pragma unroll
        for (int j = 0; j < 4; j++)
            #pragma unroll
            for (int r = 0; r < 4; r++) zc[j][r] = 0.f;
        #pragma unroll
        for (int kc = 0; kc < 8; kc++) {
            int kb = kc*8;
            unsigned a0 = Abuf[ASWI(rlo, kb + qk)];
            unsigned a1 = Abuf[ASWI(rhi, kb + qk)];
            unsigned a2 = Abuf[ASWI(rlo, kb + qk + 4)];
            unsigned a3 = Abuf[ASWI(rhi, kb + qk + 4)];
            #pragma unroll
            for (int j = 0; j < 4; j++) {
                int nn = wn*32 + j*8 + qr;
                mma_tf32(zc[j][0], zc[j][1], zc[j][2], zc[j][3],
                         a0, a1, a2, a3,
                         Wbuf[ASWI(nn, kb + qk)], Wbuf[ASWI(nn, kb + qk + 4)]);
            }
        }
        #pragma unroll
        for (int j = 0; j < 4; j++) {
            int lc = wn*32 + j*8 + 2*qk;
            int gc = t*64 + lc;
            float z0 = gelu_exact(zc[j][0] + b1[gc]);
            float z1 = gelu_exact(zc[j][1] + b1[gc+1]);
            float z2 = gelu_exact(zc[j][2] + b1[gc]);
            float z3 = gelu_exact(zc[j][3] + b1[gc+1]);
            *(float2*)(&Zbuf[ASWI(rlo, lc)]) = make_float2(z0, z1);
            *(float2*)(&Zbuf[ASWI(rhi, lc)]) = make_float2(z2, z3);
        }
        __syncthreads();

        #pragma unroll
        for (int i = 0; i < 4; i++) {
            int idx = tid + i*256;
            int r = idx >> 4, c4 = (idx & 15) << 2;
            float4 w = *(const float4*)(W2 + (size_t)r*256 + t*64 + c4);
            *(float4*)(&Wbuf[ASWI(r, c4)]) = w;
        }
        __syncthreads();

        #pragma unroll
        for (int kc = 0; kc < 8; kc++) {
            int kb = kc*8;
            unsigned a0 = Zbuf[ASWI(rlo, kb + qk)];
            unsigned a1 = Zbuf[ASWI(rhi, kb + qk)];
            unsigned a2 = Zbuf[ASWI(rlo, kb + qk + 4)];
            unsigned a3 = Zbuf[ASWI(rhi, kb + qk + 4)];
            #pragma unroll
            for (int j = 0; j < 4; j++) {
                int nn = wn*32 + j*8 + qr;
                mma_tf32(d[j][0], d[j][1], d[j][2], d[j][3],
                         a0, a1, a2, a3,
                         Wbuf[ASWI(nn, kb + qk)], Wbuf[ASWI(nn, kb + qk + 4)]);
            }
        }
        __syncthreads();
    }

    // ---- epilogue: hn = h' + ff2out ----
    #pragma unroll
    for (int j = 0; j < 4; j++) {
        int gc = wn*32 + j*8 + 2*qk;
        float2 hlo = *(float2*)(&Hbuf[rlo*66 + gc]);
        float2 hhi = *(float2*)(&Hbuf[rhi*66 + gc]);
        float v0 = d[j][0] + b2[gc]   + hlo.x;
        float v1 = d[j][1] + b2[gc+1] + hlo.y;
        float v2 = d[j][2] + b2[gc]   + hhi.x;
        float v3 = d[j][3] + b2[gc+1] + hhi.y;
        if (grlo < MROWS) *(float2*)(h + (size_t)grlo*64 + gc) = make_float2(v0, v1);
        if (grhi < MROWS) *(float2*)(h + (size_t)grhi*64 + gc) = make_float2(v2, v3);
        *(float2*)(&Hbuf[rlo*66 + gc]) = make_float2(v0, v1);
        *(float2*)(&Hbuf[rhi*66 + gc]) = make_float2(v2, v3);
    }

    if (ln1g == nullptr) return;
    __syncthreads();

    for (int rr = warp; rr < 64; rr += 8) {
        int grow = row0 + rr;
        if (grow >= MROWS) break;
        float2 v = *(float2*)(&Hbuf[rr*66 + 2*lane]);
        float mu = warp_sum(v.x + v.y) * (1.0f/64.0f);
        float a0 = v.x - mu, a1 = v.y - mu;
        float var = warp_sum(a0*a0 + a1*a1) * (1.0f/64.0f);
        float rs = rsqrtf(var + EPS);
        float2 gg = ((const float2*)ln1g)[lane];
        float2 bb = ((const float2*)ln1b)[lane];
        ((float2*)(y + (size_t)grow*64))[lane] =
            make_float2(a0*rs*gg.x + bb.x, a1*rs*gg.y + bb.y);
    }
}

// ---------------- tensor-core flash attention --------------------------------
#define KSTR 12
#define VSTR 308

__global__ void __launch_bounds__(320) attn_kernel(const float* __restrict__ qkv,
                                                   float* __restrict__ o) {
    __shared__ unsigned Ks[304*KSTR];
    __shared__ unsigned Vt[8*VSTR];
    int n = blockIdx.x >> 3;
    int h = blockIdx.x & 7;
    int tid = threadIdx.x, warp = tid >> 5, lane = tid & 31;
    int gr = lane >> 2, t4 = lane & 3;
    const float* base = qkv + (size_t)n*SS*(3*DD) + h*HD;

    for (int i = tid; i < 304*8; i += 320) {
        int s = i >> 3, d = i & 7;
        float kv = 0.f, vv = 0.f;
        if (s < SS) {
            const float* rp = base + (size_t)s*(3*DD);
            kv = rp[DD + d];
            vv = rp[2*DD + d];
        }
        Ks[s*KSTR + d] = __float_as_uint(kv);
        Vt[d*VSTR + s] = __float_as_uint(vv);
    }
    __syncthreads();

    const float sc = 0.35355339059327373f * 1.4426950408889634f;

    for (int tile = warp; tile < 19; tile += 10) {
        int q0 = tile*16;
        int r0 = min(q0 + gr, SS-1);
        int r1 = min(q0 + gr + 8, SS-1);
        const float* qp0 = base + (size_t)r0*(3*DD);
        const float* qp1 = base + (size_t)r1*(3*DD);
        unsigned qa0 = __float_as_uint(qp0[t4]*sc);
        unsigned qa1 = __float_as_uint(qp1[t4]*sc);
        unsigned qa2 = __float_as_uint(qp0[t4+4]*sc);
        unsigned qa3 = __float_as_uint(qp1[t4+4]*sc);

        float o0=0.f, o1=0.f, o2=0.f, o3=0.f;
        float l0=0.f, l1=0.f;

        #pragma unroll 2
        for (int kt = 0; kt < 38; kt++) {
            int kb = kt*8;
            unsigned b0 = Ks[(kb + gr)*KSTR + t4];
            unsigned b1 = Ks[(kb + gr)*KSTR + t4 + 4];
            float c0=0.f, c1=0.f, c2=0.f, c3=0.f;
            mma_tf32(c0, c1, c2, c3, qa0, qa1, qa2, qa3, b0, b1);

            float p0, p1, p2, p3;
            asm("ex2.approx.f32 %0, %1;" : "=f"(p0) : "f"(c0));
            asm("ex2.approx.f32 %0, %1;" : "=f"(p1) : "f"(c1));
            asm("ex2.approx.f32 %0, %1;" : "=f"(p2) : "f"(c2));
            asm("ex2.approx.f32 %0, %1;" : "=f"(p3) : "f"(c3));
            if (kt == 37) {
                if (kb + 2*t4     > 300) { p0 = 0.f; p2 = 0.f; }
                if (kb + 2*t4 + 1 > 300) { p1 = 0.f; p3 = 0.f; }
            }
            l0 += p0 + p1;
            l1 += p2 + p3;

            int srcA = (lane & 0x1c) | (t4 >> 1);
            int srcB = srcA + 2;
            float s0 = __shfl_sync(0xffffffffu, p0, srcA);
            float s1 = __shfl_sync(0xffffffffu, p1, srcA);
            float s2 = __shfl_sync(0xffffffffu, p2, srcA);
            float s3 = __shfl_sync(0xffffffffu, p3, srcA);
            float s4 = __shfl_sync(0xffffffffu, p0, srcB);
            float s5 = __shfl_sync(0xffffffffu, p1, srcB);
            float s6 = __shfl_sync(0xffffffffu, p2, srcB);
            float s7 = __shfl_sync(0xffffffffu, p3, srcB);
            bool oddc = (t4 & 1);
            unsigned pa0 = __float_as_uint(oddc ? s1 : s0);
            unsigned pa1 = __float_as_uint(oddc ? s3 : s2);
            unsigned pa2 = __float_as_uint(oddc ? s5 : s4);
            unsigned pa3 = __float_as_uint(oddc ? s7 : s6);

            unsigned vb0 = Vt[gr*VSTR + kb + t4];
            unsigned vb1 = Vt[gr*VSTR + kb + t4 + 4];
            mma_tf32(o0, o1, o2, o3, pa0, pa1, pa2, pa3, vb0, vb1);
        }

        l0 += __shfl_xor_sync(0xffffffffu, l0, 1);
        l0 += __shfl_xor_sync(0xffffffffu, l0, 2);
        l1 += __shfl_xor_sync(0xffffffffu, l1, 1);
        l1 += __shfl_xor_sync(0xffffffffu, l1, 2);
        float inv0 = 1.0f / l0, inv1 = 1.0f / l1;

        int row0g = q0 + gr, row1g = q0 + gr + 8;
        if (row0g < SS)
            *(float2*)(o + ((size_t)n*SS + row0g)*DD + h*HD + 2*t4) =
                make_float2(o0*inv0, o1*inv0);
        if (row1g < SS)
            *(float2*)(o + ((size_t)n*SS + row1g)*DD + h*HD + 2*t4) =
                make_float2(o2*inv1, o3*inv1);
    }
}

// ---------------- cls pool over edges + LayerNorm ----------------------------
__global__ void pool_kernel(const float* __restrict__ g, const float* __restrict__ bt) {
    int warp = threadIdx.x >> 5;
    int lane = threadIdx.x & 31;
    if (warp >= BB) return;
    int b = warp;
    float v0 = 0.f, v1 = 0.f;
    for (int e = 0; e < EE; e++) {
        size_t base = ((size_t)(b*EE + e)*SS)*DD;
        v0 += g_h[base + lane];
        v1 += g_h[base + lane + 32];
    }
    v0 *= (1.0f/EE); v1 *= (1.0f/EE);
    float mu = warp_sum(v0 + v1) * (1.0f/64.0f);
    float a0 = v0 - mu, a1 = v1 - mu;
    float var = warp_sum(a0*a0 + a1*a1) * (1.0f/64.0f);
    float rs = rsqrtf(var + EPS);
    g_feat[b*DD + lane]    = a0*rs*g[lane]    + bt[lane];
    g_feat[b*DD + lane+32] = a1*rs*g[lane+32] + bt[lane+32];
}

// ---------------- head MLP ---------------------------------------------------
__global__ void head1_kernel(const float* __restrict__ w, const float* __restrict__ bias) {
    __shared__ float f[DD];
    int b = blockIdx.x, d = threadIdx.x;
    f[d] = g_feat[b*DD + d];
    __syncthreads();
    float acc = bias[d];
    #pragma unroll 8
    for (int k = 0; k < DD; k++) acc = fmaf(f[k], w[d*DD + k], acc);
    g_feat2[b*DD + d] = gelu_exact(acc);
}

__global__ void head2_kernel(const float* __restrict__ w, const float* __restrict__ bias,
                             float* __restrict__ out) {
    __shared__ float f[DD];
    int b = blockIdx.x, c = threadIdx.x;
    f[c] = g_feat2[b*DD + c];
    __syncthreads();
    if (c >= NCLS) return;
    float acc = bias[c];
    #pragma unroll 8
    for (int k = 0; k < DD; k++) acc = fmaf(f[k], w[c*DD + k], acc);
    out[b*NCLS + c] = acc;
}

// ---------------- launcher ---------------------------------------------------
extern "C" void kernel_launch(void* const* d_in, const int* in_sizes, int n_in,
                              void* d_out, int out_size) {
    const float* x       = (const float*)d_in[0];
    const float* embed_w = (const float*)d_in[1];
    const float* embed_b = (const float*)d_in[2];
    const float* eln_g   = (const float*)d_in[3];
    const float* eln_b   = (const float*)d_in[4];
    const float* cls     = (const float*)d_in[5];
    const float* qkv_w   = (const float*)d_in[6];
    const float* qkv_b   = (const float*)d_in[7];
    const float* out_w   = (const float*)d_in[8];
    const float* out_b   = (const float*)d_in[9];
    const float* ln1_g   = (const float*)d_in[10];
    const float* ln1_b   = (const float*)d_in[11];
    const float* ln2_g   = (const float*)d_in[12];
    const float* ln2_b   = (const float*)d_in[13];
    const float* ff1_w   = (const float*)d_in[14];
    const float* ff1_b   = (const float*)d_in[15];
    const float* ff2_w   = (const float*)d_in[16];
    const float* ff2_b   = (const float*)d_in[17];
    const float* norm_g  = (const float*)d_in[18];
    const float* norm_b  = (const float*)d_in[19];
    const float* h1_w    = (const float*)d_in[20];
    const float* h1_b    = (const float*)d_in[21];
    const float* h2_w    = (const float*)d_in[22];
    const float* h2_b    = (const float*)d_in[23];
    float* out = (float*)d_out;

    float *hbuf, *ybuf, *qkvbuf, *obuf;
    cudaGetSymbolAddress((void**)&hbuf,   g_h);
    cudaGetSymbolAddress((void**)&ybuf,   g_y);
    cudaGetSymbolAddress((void**)&qkvbuf, g_qkv);
    cudaGetSymbolAddress((void**)&obuf,   g_o);

    cudaFuncSetAttribute(half_layer,
                         cudaFuncAttributeMaxDynamicSharedMemorySize, HSM_TOTAL);

    const int rows_grid = (MROWS + 7) / 8;
    const int gm128 = (MROWS + 127) / 128;  // 941
    const int gm64  = (MROWS + 63) / 64;    // 1882

    embed_kernel<<<rows_grid, 256>>>(x, embed_w, embed_b, eln_g, eln_b, cls,
                                     ln1_g, ln1_b);

    for (int l = 0; l < LL; l++) {
        qkv_gemm<<<gm128, 256>>>(ybuf, qkv_w + (size_t)l*3*DD*DD,
                                 qkv_b + l*3*DD, qkvbuf);
        attn_kernel<<<NN*HH, 320>>>(qkvbuf, obuf);
        const float* nlg = (l < LL-1) ? (ln1_g + (l+1)*DD) : nullptr;
        const float* nlb = (l < LL-1) ? (ln1_b + (l+1)*DD) : nullptr;
        half_layer<<<gm64, 256, HSM_TOTAL>>>(
            obuf, out_w + (size_t)l*DD*DD, out_b + l*DD,
            hbuf, ln2_g + l*DD, ln2_b + l*DD,
            ff1_w + (size_t)l*FFD*DD, ff1_b + l*FFD,
            ff2_w + (size_t)l*DD*FFD, ff2_b + l*DD,
            nlg, nlb, ybuf);
    }

    pool_kernel<<<1, 512>>>(norm_g, norm_b);
    head1_kernel<<<BB, DD>>>(h1_w, h1_b);
    head2_kernel<<<BB, DD>>>(h2_w, h2_b, out);
}

// round 12
// speedup vs baseline: 1.2779x; 1.1694x over previous
#include <cuda_runtime.h>
#include <cuda_bf16.h>
#include <math.h>

// Problem constants
#define BB 16
#define EE 25
#define TT 300
#define CC 3
#define DD 64
#define HH 8
#define FFD 256
#define LL 4
#define NCLS 60
#define NN (BB*EE)        // 400
#define SS (TT+1)         // 301
#define HD (DD/HH)        // 8
#define MROWS (NN*SS)     // 120400
#define EPS 1e-5f

// ---------------- scratch buffers -------------------------------------------
__device__ float g_h[MROWS*DD];      // residual stream
__device__ float g_y[MROWS*DD];      // LN output
__device__ float g_qkv[MROWS*3*DD];  // qkv
__device__ float g_o[MROWS*DD];      // attention output
__device__ float g_feat[BB*DD];
__device__ float g_feat2[BB*DD];

// ---------------- helpers ---------------------------------------------------
__device__ __forceinline__ float warp_sum(float v) {
    #pragma unroll
    for (int o = 16; o; o >>= 1) v += __shfl_xor_sync(0xffffffffu, v, o);
    return v;
}

__device__ __forceinline__ float gelu_exact(float x) {
    return 0.5f * x * (1.0f + erff(x * 0.70710678118654752f));
}

__device__ __forceinline__ void mma_tf32(float& c0, float& c1, float& c2, float& c3,
                                         unsigned a0, unsigned a1, unsigned a2, unsigned a3,
                                         unsigned b0, unsigned b1) {
    asm volatile(
        "mma.sync.aligned.m16n8k8.row.col.f32.tf32.tf32.f32 "
        "{%0,%1,%2,%3}, {%4,%5,%6,%7}, {%8,%9}, {%0,%1,%2,%3};"
        : "+f"(c0), "+f"(c1), "+f"(c2), "+f"(c3)
        : "r"(a0), "r"(a1), "r"(a2), "r"(a3), "r"(b0), "r"(b1));
}

// pack two f32 -> bf16x2 (lo = first arg)
__device__ __forceinline__ unsigned pk_bf16(float lo, float hi) {
    unsigned r;
    asm("cvt.rn.bf16x2.f32 %0, %1, %2;" : "=r"(r) : "f"(hi), "f"(lo));
    return r;
}

__device__ __forceinline__ void mma_bf16_k8(float& c0, float& c1, float& c2, float& c3,
                                            unsigned a0, unsigned a1, unsigned b0) {
    asm volatile(
        "mma.sync.aligned.m16n8k8.row.col.f32.bf16.bf16.f32 "
        "{%0,%1,%2,%3}, {%4,%5}, {%6}, {%0,%1,%2,%3};"
        : "+f"(c0), "+f"(c1), "+f"(c2), "+f"(c3)
        : "r"(a0), "r"(a1), "r"(b0));
}

__device__ __forceinline__ void mma_bf16_k16(float& c0, float& c1, float& c2, float& c3,
                                             unsigned a0, unsigned a1, unsigned a2, unsigned a3,
                                             unsigned b0, unsigned b1) {
    asm volatile(
        "mma.sync.aligned.m16n8k16.row.col.f32.bf16.bf16.f32 "
        "{%0,%1,%2,%3}, {%4,%5,%6,%7}, {%8,%9}, {%0,%1,%2,%3};"
        : "+f"(c0), "+f"(c1), "+f"(c2), "+f"(c3)
        : "r"(a0), "r"(a1), "r"(a2), "r"(a3), "r"(b0), "r"(b1));
}

#define ASWI(r,c) ((r)*64 + (((c) ^ (((r)&7)<<2))))

// ---------------- embed + LN + cls + pos + fused ln1[0] ----------------------
__global__ void embed_kernel(const float* __restrict__ x,
                             const float* __restrict__ ew,
                             const float* __restrict__ ebias,
                             const float* __restrict__ eg,
                             const float* __restrict__ ebt,
                             const float* __restrict__ cls,
                             const float* __restrict__ l1g,
                             const float* __restrict__ l1b) {
    int warp = (blockIdx.x * blockDim.x + threadIdx.x) >> 5;
    int lane = threadIdx.x & 31;
    if (warp >= MROWS) return;
    int n = warp / SS, s = warp % SS;
    int b = n / EE, e = n % EE;

    float v0, v1;
    if (s == 0) {
        v0 = cls[lane];
        v1 = cls[lane + 32];
    } else {
        int t = s - 1;
        float x0 = x[((b*CC + 0)*TT + t)*EE + e];
        float x1 = x[((b*CC + 1)*TT + t)*EE + e];
        float x2 = x[((b*CC + 2)*TT + t)*EE + e];
        int d0 = lane, d1 = lane + 32;
        v0 = ebias[d0] + x0*ew[d0*3] + x1*ew[d0*3+1] + x2*ew[d0*3+2];
        v1 = ebias[d1] + x0*ew[d1*3] + x1*ew[d1*3+1] + x2*ew[d1*3+2];
        float mu = warp_sum(v0 + v1) * (1.0f/64.0f);
        float a0 = v0 - mu, a1 = v1 - mu;
        float var = warp_sum(a0*a0 + a1*a1) * (1.0f/64.0f);
        float r = rsqrtf(var + EPS);
        v0 = a0 * r * eg[d0] + ebt[d0];
        v1 = a1 * r * eg[d1] + ebt[d1];
    }
    const float kfreq = -0.14391565f; // -ln(10000)/64
    {
        int d0 = lane;
        int i = d0 >> 1;
        float ang = (float)s * __expf((float)(2*i) * kfreq);
        v0 += (d0 & 1) ? cosf(ang) : sinf(ang);
        int d1 = lane + 32;
        i = d1 >> 1;
        ang = (float)s * __expf((float)(2*i) * kfreq);
        v1 += (d1 & 1) ? cosf(ang) : sinf(ang);
    }
    g_h[warp*DD + lane]      = v0;
    g_h[warp*DD + lane + 32] = v1;
    // fused ln1[0]
    float mu = warp_sum(v0 + v1) * (1.0f/64.0f);
    float a0 = v0 - mu, a1 = v1 - mu;
    float var = warp_sum(a0*a0 + a1*a1) * (1.0f/64.0f);
    float rs = rsqrtf(var + EPS);
    g_y[warp*DD + lane]      = a0*rs*l1g[lane]    + l1b[lane];
    g_y[warp*DD + lane + 32] = a1*rs*l1g[lane+32] + l1b[lane+32];
}

// ---------------- qkv GEMM: one N-tile per block (grid 941 x 3) --------------
__global__ void __launch_bounds__(256, 3)
qkv_gemm(const float* __restrict__ A, const float* __restrict__ W,
         const float* __restrict__ bias, float* __restrict__ out) {
    __shared__ unsigned As[128*64];
    __shared__ unsigned Bs[64*64];
    int tid = threadIdx.x;
    int warp = tid >> 5, lane = tid & 31;
    int wm = warp >> 1, wn = warp & 1;
    int row0 = blockIdx.x * 128;
    int nt = blockIdx.y;
    int qr = lane >> 2, qk = lane & 3;

    #pragma unroll
    for (int i = 0; i < 8; i++) {
        int idx = tid + i*256;
        int r = idx >> 4, c4 = (idx & 15) << 2;
        int gr = row0 + r;
        float4 v = (gr < MROWS) ? *(const float4*)(A + (size_t)gr*64 + c4)
                                : make_float4(0.f,0.f,0.f,0.f);
        *(float4*)(&As[ASWI(r, c4)]) = v;
    }
    #pragma unroll
    for (int i = 0; i < 4; i++) {
        int idx = tid + i*256;
        int r = idx >> 4, c4 = (idx & 15) << 2;
        float4 v = *(const float4*)(W + (size_t)(nt*64 + r)*64 + c4);
        *(float4*)(&Bs[ASWI(r, c4)]) = v;
    }
    __syncthreads();

    float c[2][4][4];
    #pragma unroll
    for (int i = 0; i < 2; i++)
        #pragma unroll
        for (int j = 0; j < 4; j++)
            #pragma unroll
            for (int r = 0; r < 4; r++) c[i][j][r] = 0.f;

    #pragma unroll
    for (int kc = 0; kc < 8; kc++) {
        int kb = kc*8;
        unsigned a[2][4], b[4][2];
        #pragma unroll
        for (int i = 0; i < 2; i++) {
            int r = wm*32 + i*16 + qr;
            a[i][0] = As[ASWI(r,     kb + qk)];
            a[i][1] = As[ASWI(r + 8, kb + qk)];
            a[i][2] = As[ASWI(r,     kb + qk + 4)];
            a[i][3] = As[ASWI(r + 8, kb + qk + 4)];
        }
        #pragma unroll
        for (int j = 0; j < 4; j++) {
            int nn = wn*32 + j*8 + qr;
            b[j][0] = Bs[ASWI(nn, kb + qk)];
            b[j][1] = Bs[ASWI(nn, kb + qk + 4)];
        }
        #pragma unroll
        for (int i = 0; i < 2; i++)
            #pragma unroll
            for (int j = 0; j < 4; j++)
                mma_tf32(c[i][j][0], c[i][j][1], c[i][j][2], c[i][j][3],
                         a[i][0], a[i][1], a[i][2], a[i][3], b[j][0], b[j][1]);
    }

    #pragma unroll
    for (int i = 0; i < 2; i++) {
        #pragma unroll
        for (int half = 0; half < 2; half++) {
            int gr = row0 + wm*32 + i*16 + qr + half*8;
            if (gr >= MROWS) continue;
            #pragma unroll
            for (int j = 0; j < 4; j++) {
                int gc = nt*64 + wn*32 + j*8 + qk*2;
                float v0 = c[i][j][half*2]     + bias[gc];
                float v1 = c[i][j][half*2 + 1] + bias[gc + 1];
                *(float2*)(out + (size_t)gr*192 + gc) = make_float2(v0, v1);
            }
        }
    }
}

// ---------------- fused half layer (dynamic smem, 3 CTAs/SM) -----------------
#define HSM_A 0
#define HSM_Z 16384
#define HSM_W 32768
#define HSM_H 49152
#define HSM_TOTAL 66048   // 49152 + 64*66*4

__global__ void __launch_bounds__(256, 3)
half_layer(const float* __restrict__ o,
           const float* __restrict__ Wout, const float* __restrict__ bout,
           float* __restrict__ h,
           const float* __restrict__ ln2g, const float* __restrict__ ln2b,
           const float* __restrict__ W1, const float* __restrict__ b1,
           const float* __restrict__ W2, const float* __restrict__ b2,
           const float* __restrict__ ln1g, const float* __restrict__ ln1b,
           float* __restrict__ y) {
    extern __shared__ __align__(16) char sm[];
    unsigned* Abuf = (unsigned*)(sm + HSM_A);   // 64x64
    unsigned* Zbuf = (unsigned*)(sm + HSM_Z);   // 64x64
    unsigned* Wbuf = (unsigned*)(sm + HSM_W);   // 64x64
    float*    Hbuf = (float*)(sm + HSM_H);      // 64 x stride 66

    int tid = threadIdx.x;
    int warp = tid >> 5, lane = tid & 31;
    int wm = warp >> 1, wn = warp & 1;
    int row0 = blockIdx.x * 64;
    int qr = lane >> 2, qk = lane & 3;
    int rlo = wm*16 + qr, rhi = rlo + 8;
    int grlo = row0 + rlo, grhi = row0 + rhi;

    // ---- stage o + Wout ----
    #pragma unroll
    for (int i = 0; i < 4; i++) {
        int idx = tid + i*256;
        int r = idx >> 4, c4 = (idx & 15) << 2;
        int gr = row0 + r;
        float4 v = (gr < MROWS) ? *(const float4*)(o + (size_t)gr*64 + c4)
                                : make_float4(0.f,0.f,0.f,0.f);
        *(float4*)(&Abuf[ASWI(r, c4)]) = v;
        float4 w = *(const float4*)(Wout + (size_t)r*64 + c4);
        *(float4*)(&Wbuf[ASWI(r, c4)]) = w;
    }
    __syncthreads();

    // ---- out-proj mma -> residual into Hbuf ----
    {
        float c[4][4];
        #pragma unroll
        for (int j = 0; j < 4; j++)
            #pragma unroll
            for (int r = 0; r < 4; r++) c[j][r] = 0.f;
        #pragma unroll
        for (int kc = 0; kc < 8; kc++) {
            int kb = kc*8;
            unsigned a0 = Abuf[ASWI(rlo, kb + qk)];
            unsigned a1 = Abuf[ASWI(rhi, kb + qk)];
            unsigned a2 = Abuf[ASWI(rlo, kb + qk + 4)];
            unsigned a3 = Abuf[ASWI(rhi, kb + qk + 4)];
            #pragma unroll
            for (int j = 0; j < 4; j++) {
                int nn = wn*32 + j*8 + qr;
                mma_tf32(c[j][0], c[j][1], c[j][2], c[j][3],
                         a0, a1, a2, a3,
                         Wbuf[ASWI(nn, kb + qk)], Wbuf[ASWI(nn, kb + qk + 4)]);
            }
        }
        #pragma unroll
        for (int j = 0; j < 4; j++) {
            int gc = wn*32 + j*8 + 2*qk;
            float hv0 = c[j][0] + bout[gc], hv1 = c[j][1] + bout[gc+1];
            float hv2 = c[j][2] + bout[gc], hv3 = c[j][3] + bout[gc+1];
            if (grlo < MROWS) { float2 t = *(const float2*)(h + (size_t)grlo*64 + gc); hv0 += t.x; hv1 += t.y; }
            if (grhi < MROWS) { float2 t = *(const float2*)(h + (size_t)grhi*64 + gc); hv2 += t.x; hv3 += t.y; }
            *(float2*)(&Hbuf[rlo*66 + gc]) = make_float2(hv0, hv1);
            *(float2*)(&Hbuf[rhi*66 + gc]) = make_float2(hv2, hv3);
        }
    }
    __syncthreads();

    // ---- LN2 -> y2 into Abuf ----
    for (int rr = warp; rr < 64; rr += 8) {
        float2 v = *(float2*)(&Hbuf[rr*66 + 2*lane]);
        float mu = warp_sum(v.x + v.y) * (1.0f/64.0f);
        float a0 = v.x - mu, a1 = v.y - mu;
        float var = warp_sum(a0*a0 + a1*a1) * (1.0f/64.0f);
        float rs = rsqrtf(var + EPS);
        float2 gg = ((const float2*)ln2g)[lane];
        float2 bb = ((const float2*)ln2b)[lane];
        *(float2*)(&Abuf[ASWI(rr, 2*lane)]) =
            make_float2(a0*rs*gg.x + bb.x, a1*rs*gg.y + bb.y);
    }
    __syncthreads();

    // ---- FF: z stays in smem ----
    float d[4][4];
    #pragma unroll
    for (int j = 0; j < 4; j++)
        #pragma unroll
        for (int r = 0; r < 4; r++) d[j][r] = 0.f;

    for (int t = 0; t < 4; t++) {
        #pragma unroll
        for (int i = 0; i < 4; i++) {
            int idx = tid + i*256;
            int r = idx >> 4, c4 = (idx & 15) << 2;
            float4 w = *(const float4*)(W1 + (size_t)(t*64 + r)*64 + c4);
            *(float4*)(&Wbuf[ASWI(r, c4)]) = w;
        }
        __syncthreads();

        float zc[4][4];
        #pragma unroll
        for (int j = 0; j < 4; j++)
            #pragma unroll
            for (int r = 0; r < 4; r++) zc[j][r] = 0.f;
        #pragma unroll
        for (int kc = 0; kc < 8; kc++) {
            int kb = kc*8;
            unsigned a0 = Abuf[ASWI(rlo, kb + qk)];
            unsigned a1 = Abuf[ASWI(rhi, kb + qk)];
            unsigned a2 = Abuf[ASWI(rlo, kb + qk + 4)];
            unsigned a3 = Abuf[ASWI(rhi, kb + qk + 4)];
            #pragma unroll
            for (int j = 0; j < 4; j++) {
                int nn = wn*32 + j*8 + qr;
                mma_tf32(zc[j][0], zc[j][1], zc[j][2], zc[j][3],
                         a0, a1, a2, a3,
                         Wbuf[ASWI(nn, kb + qk)], Wbuf[ASWI(nn, kb + qk + 4)]);
            }
        }
        #pragma unroll
        for (int j = 0; j < 4; j++) {
            int lc = wn*32 + j*8 + 2*qk;
            int gc = t*64 + lc;
            float z0 = gelu_exact(zc[j][0] + b1[gc]);
            float z1 = gelu_exact(zc[j][1] + b1[gc+1]);
            float z2 = gelu_exact(zc[j][2] + b1[gc]);
            float z3 = gelu_exact(zc[j][3] + b1[gc+1]);
            *(float2*)(&Zbuf[ASWI(rlo, lc)]) = make_float2(z0, z1);
            *(float2*)(&Zbuf[ASWI(rhi, lc)]) = make_float2(z2, z3);
        }
        __syncthreads();

        #pragma unroll
        for (int i = 0; i < 4; i++) {
            int idx = tid + i*256;
            int r = idx >> 4, c4 = (idx & 15) << 2;
            float4 w = *(const float4*)(W2 + (size_t)r*256 + t*64 + c4);
            *(float4*)(&Wbuf[ASWI(r, c4)]) = w;
        }
        __syncthreads();

        #pragma unroll
        for (int kc = 0; kc < 8; kc++) {
            int kb = kc*8;
            unsigned a0 = Zbuf[ASWI(rlo, kb + qk)];
            unsigned a1 = Zbuf[ASWI(rhi, kb + qk)];
            unsigned a2 = Zbuf[ASWI(rlo, kb + qk + 4)];
            unsigned a3 = Zbuf[ASWI(rhi, kb + qk + 4)];
            #pragma unroll
            for (int j = 0; j < 4; j++) {
                int nn = wn*32 + j*8 + qr;
                mma_tf32(d[j][0], d[j][1], d[j][2], d[j][3],
                         a0, a1, a2, a3,
                         Wbuf[ASWI(nn, kb + qk)], Wbuf[ASWI(nn, kb + qk + 4)]);
            }
        }
        __syncthreads();
    }

    // ---- epilogue: hn = h' + ff2out ----
    #pragma unroll
    for (int j = 0; j < 4; j++) {
        int gc = wn*32 + j*8 + 2*qk;
        float2 hlo = *(float2*)(&Hbuf[rlo*66 + gc]);
        float2 hhi = *(float2*)(&Hbuf[rhi*66 + gc]);
        float v0 = d[j][0] + b2[gc]   + hlo.x;
        float v1 = d[j][1] + b2[gc+1] + hlo.y;
        float v2 = d[j][2] + b2[gc]   + hhi.x;
        float v3 = d[j][3] + b2[gc+1] + hhi.y;
        if (grlo < MROWS) *(float2*)(h + (size_t)grlo*64 + gc) = make_float2(v0, v1);
        if (grhi < MROWS) *(float2*)(h + (size_t)grhi*64 + gc) = make_float2(v2, v3);
        *(float2*)(&Hbuf[rlo*66 + gc]) = make_float2(v0, v1);
        *(float2*)(&Hbuf[rhi*66 + gc]) = make_float2(v2, v3);
    }

    if (ln1g == nullptr) return;
    __syncthreads();

    for (int rr = warp; rr < 64; rr += 8) {
        int grow = row0 + rr;
        if (grow >= MROWS) break;
        float2 v = *(float2*)(&Hbuf[rr*66 + 2*lane]);
        float mu = warp_sum(v.x + v.y) * (1.0f/64.0f);
        float a0 = v.x - mu, a1 = v.y - mu;
        float var = warp_sum(a0*a0 + a1*a1) * (1.0f/64.0f);
        float rs = rsqrtf(var + EPS);
        float2 gg = ((const float2*)ln1g)[lane];
        float2 bb = ((const float2*)ln1b)[lane];
        ((float2*)(y + (size_t)grow*64))[lane] =
            make_float2(a0*rs*gg.x + bb.x, a1*rs*gg.y + bb.y);
    }
}

// ---------------- bf16 flash attention (zero-shuffle P remap) ----------------
// block = one (n,h), 320 threads. S via 2x m16n8k8.bf16; P packs straight into
// the m16n8k16 A-fragment; PV via one m16n8k16.bf16.
#define VROW 156   // 312 keys as bf16 pairs; stride 156 words -> conflict-free

__global__ void __launch_bounds__(320) attn_kernel(const float* __restrict__ qkv,
                                                   float* __restrict__ o) {
    __shared__ unsigned Kb[304*4];   // K[key][d] bf16 pairs (d pairs)
    __shared__ unsigned Vt[8*VROW];  // V^T[d][key] bf16 pairs (key pairs)
    int n = blockIdx.x >> 3;
    int h = blockIdx.x & 7;
    int tid = threadIdx.x, warp = tid >> 5, lane = tid & 31;
    int gr = lane >> 2, qk = lane & 3;
    const float* base = qkv + (size_t)n*SS*(3*DD) + h*HD;

    // stage K as bf16 pairs (key-major)
    for (int i = tid; i < 304*4; i += 320) {
        int s = i >> 2, dp = i & 3;
        float k0 = 0.f, k1 = 0.f;
        if (s < SS) {
            const float* rp = base + (size_t)s*(3*DD) + DD + 2*dp;
            k0 = rp[0]; k1 = rp[1];
        }
        Kb[i] = pk_bf16(k0, k1);
    }
    // stage V transposed as bf16 key-pairs
    for (int i = tid; i < 8*152; i += 320) {
        int d = i / 152, kp = i % 152;
        int s0 = 2*kp, s1 = 2*kp + 1;
        float v0 = (s0 < SS) ? base[(size_t)s0*(3*DD) + 2*DD + d] : 0.f;
        float v1 = (s1 < SS) ? base[(size_t)s1*(3*DD) + 2*DD + d] : 0.f;
        Vt[d*VROW + kp] = pk_bf16(v0, v1);
    }
    __syncthreads();

    const float sc = 0.35355339059327373f * 1.4426950408889634f; // 1/sqrt(8)*log2e

    for (int tile = warp; tile < 19; tile += 10) {
        int q0 = tile*16;
        int r0 = min(q0 + gr, SS-1);
        int r1 = min(q0 + gr + 8, SS-1);
        const float* qp0 = base + (size_t)r0*(3*DD) + 2*qk;
        const float* qp1 = base + (size_t)r1*(3*DD) + 2*qk;
        unsigned qa0 = pk_bf16(qp0[0]*sc, qp0[1]*sc);
        unsigned qa1 = pk_bf16(qp1[0]*sc, qp1[1]*sc);
        const float* qp0b = qp0 + 4 - 2*qk;  // base of row, for cols 4..7? no:
        // full k8 needs cols 0..7: a-frag covers only cols 2qk,2qk+1 per thread. OK.

        float o0=0.f, o1=0.f, o2=0.f, o3=0.f;
        float l0=0.f, l1=0.f;
        (void)qp0b;

        #pragma unroll 2
        for (int kt = 0; kt < 19; kt++) {
            int kb = kt*16;
            unsigned b0 = Kb[(kb + gr)*4 + qk];
            unsigned b1 = Kb[(kb + 8 + gr)*4 + qk];
            float c0=0.f, c1=0.f, c2=0.f, c3=0.f;
            float e0=0.f, e1=0.f, e2=0.f, e3=0.f;
            mma_bf16_k8(c0, c1, c2, c3, qa0, qa1, b0);
            mma_bf16_k8(e0, e1, e2, e3, qa0, qa1, b1);

            float p0, p1, p2, p3, s0, s1, s2, s3;
            asm("ex2.approx.f32 %0, %1;" : "=f"(p0) : "f"(c0));
            asm("ex2.approx.f32 %0, %1;" : "=f"(p1) : "f"(c1));
            asm("ex2.approx.f32 %0, %1;" : "=f"(p2) : "f"(c2));
            asm("ex2.approx.f32 %0, %1;" : "=f"(p3) : "f"(c3));
            asm("ex2.approx.f32 %0, %1;" : "=f"(s0) : "f"(e0));
            asm("ex2.approx.f32 %0, %1;" : "=f"(s1) : "f"(e1));
            asm("ex2.approx.f32 %0, %1;" : "=f"(s2) : "f"(e2));
            asm("ex2.approx.f32 %0, %1;" : "=f"(s3) : "f"(e3));
            if (kt == 18) {   // keys 288..303; mask >300 (only in second n8)
                int k0i = kb + 8 + 2*qk;
                if (k0i     > 300) { s0 = 0.f; s2 = 0.f; }
                if (k0i + 1 > 300) { s1 = 0.f; s3 = 0.f; }
            }
            l0 += p0 + p1 + s0 + s1;
            l1 += p2 + p3 + s2 + s3;

            unsigned pa0 = pk_bf16(p0, p1);
            unsigned pa1 = pk_bf16(p2, p3);
            unsigned pa2 = pk_bf16(s0, s1);
            unsigned pa3 = pk_bf16(s2, s3);

            unsigned vb0 = Vt[gr*VROW + (kb >> 1) + qk];
            unsigned vb1 = Vt[gr*VROW + (kb >> 1) + 4 + qk];
            mma_bf16_k16(o0, o1, o2, o3, pa0, pa1, pa2, pa3, vb0, vb1);
        }

        l0 += __shfl_xor_sync(0xffffffffu, l0, 1);
        l0 += __shfl_xor_sync(0xffffffffu, l0, 2);
        l1 += __shfl_xor_sync(0xffffffffu, l1, 1);
        l1 += __shfl_xor_sync(0xffffffffu, l1, 2);
        float inv0 = 1.0f / l0, inv1 = 1.0f / l1;

        int row0g = q0 + gr, row1g = q0 + gr + 8;
        if (row0g < SS)
            *(float2*)(o + ((size_t)n*SS + row0g)*DD + h*HD + 2*qk) =
                make_float2(o0*inv0, o1*inv0);
        if (row1g < SS)
            *(float2*)(o + ((size_t)n*SS + row1g)*DD + h*HD + 2*qk) =
                make_float2(o2*inv1, o3*inv1);
    }
}

// ---------------- cls pool over edges + LayerNorm ----------------------------
__global__ void pool_kernel(const float* __restrict__ g, const float* __restrict__ bt) {
    int warp = threadIdx.x >> 5;
    int lane = threadIdx.x & 31;
    if (warp >= BB) return;
    int b = warp;
    float v0 = 0.f, v1 = 0.f;
    for (int e = 0; e < EE; e++) {
        size_t base = ((size_t)(b*EE + e)*SS)*DD;
        v0 += g_h[base + lane];
        v1 += g_h[base + lane + 32];
    }
    v0 *= (1.0f/EE); v1 *= (1.0f/EE);
    float mu = warp_sum(v0 + v1) * (1.0f/64.0f);
    float a0 = v0 - mu, a1 = v1 - mu;
    float var = warp_sum(a0*a0 + a1*a1) * (1.0f/64.0f);
    float rs = rsqrtf(var + EPS);
    g_feat[b*DD + lane]    = a0*rs*g[lane]    + bt[lane];
    g_feat[b*DD + lane+32] = a1*rs*g[lane+32] + bt[lane+32];
}

// ---------------- head MLP ---------------------------------------------------
__global__ void head1_kernel(const float* __restrict__ w, const float* __restrict__ bias) {
    __shared__ float f[DD];
    int b = blockIdx.x, d = threadIdx.x;
    f[d] = g_feat[b*DD + d];
    __syncthreads();
    float acc = bias[d];
    #pragma unroll 8
    for (int k = 0; k < DD; k++) acc = fmaf(f[k], w[d*DD + k], acc);
    g_feat2[b*DD + d] = gelu_exact(acc);
}

__global__ void head2_kernel(const float* __restrict__ w, const float* __restrict__ bias,
                             float* __restrict__ out) {
    __shared__ float f[DD];
    int b = blockIdx.x, c = threadIdx.x;
    f[c] = g_feat2[b*DD + c];
    __syncthreads();
    if (c >= NCLS) return;
    float acc = bias[c];
    #pragma unroll 8
    for (int k = 0; k < DD; k++) acc = fmaf(f[k], w[c*DD + k], acc);
    out[b*NCLS + c] = acc;
}

// ---------------- launcher ---------------------------------------------------
extern "C" void kernel_launch(void* const* d_in, const int* in_sizes, int n_in,
                              void* d_out, int out_size) {
    const float* x       = (const float*)d_in[0];
    const float* embed_w = (const float*)d_in[1];
    const float* embed_b = (const float*)d_in[2];
    const float* eln_g   = (const float*)d_in[3];
    const float* eln_b   = (const float*)d_in[4];
    const float* cls     = (const float*)d_in[5];
    const float* qkv_w   = (const float*)d_in[6];
    const float* qkv_b   = (const float*)d_in[7];
    const float* out_w   = (const float*)d_in[8];
    const float* out_b   = (const float*)d_in[9];
    const float* ln1_g   = (const float*)d_in[10];
    const float* ln1_b   = (const float*)d_in[11];
    const float* ln2_g   = (const float*)d_in[12];
    const float* ln2_b   = (const float*)d_in[13];
    const float* ff1_w   = (const float*)d_in[14];
    const float* ff1_b   = (const float*)d_in[15];
    const float* ff2_w   = (const float*)d_in[16];
    const float* ff2_b   = (const float*)d_in[17];
    const float* norm_g  = (const float*)d_in[18];
    const float* norm_b  = (const float*)d_in[19];
    const float* h1_w    = (const float*)d_in[20];
    const float* h1_b    = (const float*)d_in[21];
    const float* h2_w    = (const float*)d_in[22];
    const float* h2_b    = (const float*)d_in[23];
    float* out = (float*)d_out;

    float *hbuf, *ybuf, *qkvbuf, *obuf;
    cudaGetSymbolAddress((void**)&hbuf,   g_h);
    cudaGetSymbolAddress((void**)&ybuf,   g_y);
    cudaGetSymbolAddress((void**)&qkvbuf, g_qkv);
    cudaGetSymbolAddress((void**)&obuf,   g_o);

    cudaFuncSetAttribute(half_layer,
                         cudaFuncAttributeMaxDynamicSharedMemorySize, HSM_TOTAL);

    const int rows_grid = (MROWS + 7) / 8;
    const int gm128 = (MROWS + 127) / 128;  // 941
    const int gm64  = (MROWS + 63) / 64;    // 1882

    embed_kernel<<<rows_grid, 256>>>(x, embed_w, embed_b, eln_g, eln_b, cls,
                                     ln1_g, ln1_b);

    for (int l = 0; l < LL; l++) {
        qkv_gemm<<<dim3(gm128, 3), 256>>>(ybuf, qkv_w + (size_t)l*3*DD*DD,
                                          qkv_b + l*3*DD, qkvbuf);
        attn_kernel<<<NN*HH, 320>>>(qkvbuf, obuf);
        const float* nlg = (l < LL-1) ? (ln1_g + (l+1)*DD) : nullptr;
        const float* nlb = (l < LL-1) ? (ln1_b + (l+1)*DD) : nullptr;
        half_layer<<<gm64, 256, HSM_TOTAL>>>(
            obuf, out_w + (size_t)l*DD*DD, out_b + l*DD,
            hbuf, ln2_g + l*DD, ln2_b + l*DD,
            ff1_w + (size_t)l*FFD*DD, ff1_b + l*FFD,
            ff2_w + (size_t)l*DD*FFD, ff2_b + l*DD,
            nlg, nlb, ybuf);
    }

    pool_kernel<<<1, 512>>>(norm_g, norm_b);
    head1_kernel<<<BB, DD>>>(h1_w, h1_b);
    head2_kernel<<<BB, DD>>>(h2_w, h2_b, out);
}

// round 13
// speedup vs baseline: 1.5143x; 1.1849x over previous
#include <cuda_runtime.h>
#include <cuda_bf16.h>
#include <math.h>

// Problem constants
#define BB 16
#define EE 25
#define TT 300
#define CC 3
#define DD 64
#define HH 8
#define FFD 256
#define LL 4
#define NCLS 60
#define NN (BB*EE)        // 400
#define SS (TT+1)         // 301
#define HD (DD/HH)        // 8
#define MROWS (NN*SS)     // 120400
#define EPS 1e-5f

// ---------------- scratch buffers -------------------------------------------
__device__ float g_h[MROWS*DD];      // residual stream
__device__ float g_y[MROWS*DD];      // LN output
__device__ float g_qkv[MROWS*3*DD];  // qkv
__device__ float g_o[MROWS*DD];      // attention output
__device__ float g_feat[BB*DD];
__device__ float g_feat2[BB*DD];

// ---------------- helpers ---------------------------------------------------
__device__ __forceinline__ float warp_sum(float v) {
    #pragma unroll
    for (int o = 16; o; o >>= 1) v += __shfl_xor_sync(0xffffffffu, v, o);
    return v;
}

__device__ __forceinline__ float gelu_exact(float x) {
    return 0.5f * x * (1.0f + erff(x * 0.70710678118654752f));
}

__device__ __forceinline__ void mma_tf32(float& c0, float& c1, float& c2, float& c3,
                                         unsigned a0, unsigned a1, unsigned a2, unsigned a3,
                                         unsigned b0, unsigned b1) {
    asm volatile(
        "mma.sync.aligned.m16n8k8.row.col.f32.tf32.tf32.f32 "
        "{%0,%1,%2,%3}, {%4,%5,%6,%7}, {%8,%9}, {%0,%1,%2,%3};"
        : "+f"(c0), "+f"(c1), "+f"(c2), "+f"(c3)
        : "r"(a0), "r"(a1), "r"(a2), "r"(a3), "r"(b0), "r"(b1));
}

// pack two f32 -> bf16x2 (lo = first arg)
__device__ __forceinline__ unsigned pk_bf16(float lo, float hi) {
    unsigned r;
    asm("cvt.rn.bf16x2.f32 %0, %1, %2;" : "=r"(r) : "f"(hi), "f"(lo));
    return r;
}

__device__ __forceinline__ void mma_bf16_k8(float& c0, float& c1, float& c2, float& c3,
                                            unsigned a0, unsigned a1, unsigned b0) {
    asm volatile(
        "mma.sync.aligned.m16n8k8.row.col.f32.bf16.bf16.f32 "
        "{%0,%1,%2,%3}, {%4,%5}, {%6}, {%0,%1,%2,%3};"
        : "+f"(c0), "+f"(c1), "+f"(c2), "+f"(c3)
        : "r"(a0), "r"(a1), "r"(b0));
}

__device__ __forceinline__ void mma_bf16_k16(float& c0, float& c1, float& c2, float& c3,
                                             unsigned a0, unsigned a1, unsigned a2, unsigned a3,
                                             unsigned b0, unsigned b1) {
    asm volatile(
        "mma.sync.aligned.m16n8k16.row.col.f32.bf16.bf16.f32 "
        "{%0,%1,%2,%3}, {%4,%5,%6,%7}, {%8,%9}, {%0,%1,%2,%3};"
        : "+f"(c0), "+f"(c1), "+f"(c2), "+f"(c3)
        : "r"(a0), "r"(a1), "r"(a2), "r"(a3), "r"(b0), "r"(b1));
}

#define ASWI(r,c) ((r)*64 + (((c) ^ (((r)&7)<<2))))
// bf16-pair tiles: 32 words per row
#define ASW2(r,c) ((r)*32 + (((c) ^ (((r)&7)<<2))))

// ---------------- embed + LN + cls + pos + fused ln1[0] ----------------------
__global__ void embed_kernel(const float* __restrict__ x,
                             const float* __restrict__ ew,
                             const float* __restrict__ ebias,
                             const float* __restrict__ eg,
                             const float* __restrict__ ebt,
                             const float* __restrict__ cls,
                             const float* __restrict__ l1g,
                             const float* __restrict__ l1b) {
    int warp = (blockIdx.x * blockDim.x + threadIdx.x) >> 5;
    int lane = threadIdx.x & 31;
    if (warp >= MROWS) return;
    int n = warp / SS, s = warp % SS;
    int b = n / EE, e = n % EE;

    float v0, v1;
    if (s == 0) {
        v0 = cls[lane];
        v1 = cls[lane + 32];
    } else {
        int t = s - 1;
        float x0 = x[((b*CC + 0)*TT + t)*EE + e];
        float x1 = x[((b*CC + 1)*TT + t)*EE + e];
        float x2 = x[((b*CC + 2)*TT + t)*EE + e];
        int d0 = lane, d1 = lane + 32;
        v0 = ebias[d0] + x0*ew[d0*3] + x1*ew[d0*3+1] + x2*ew[d0*3+2];
        v1 = ebias[d1] + x0*ew[d1*3] + x1*ew[d1*3+1] + x2*ew[d1*3+2];
        float mu = warp_sum(v0 + v1) * (1.0f/64.0f);
        float a0 = v0 - mu, a1 = v1 - mu;
        float var = warp_sum(a0*a0 + a1*a1) * (1.0f/64.0f);
        float r = rsqrtf(var + EPS);
        v0 = a0 * r * eg[d0] + ebt[d0];
        v1 = a1 * r * eg[d1] + ebt[d1];
    }
    const float kfreq = -0.14391565f; // -ln(10000)/64
    {
        int d0 = lane;
        int i = d0 >> 1;
        float ang = (float)s * __expf((float)(2*i) * kfreq);
        v0 += (d0 & 1) ? cosf(ang) : sinf(ang);
        int d1 = lane + 32;
        i = d1 >> 1;
        ang = (float)s * __expf((float)(2*i) * kfreq);
        v1 += (d1 & 1) ? cosf(ang) : sinf(ang);
    }
    g_h[warp*DD + lane]      = v0;
    g_h[warp*DD + lane + 32] = v1;
    // fused ln1[0]
    float mu = warp_sum(v0 + v1) * (1.0f/64.0f);
    float a0 = v0 - mu, a1 = v1 - mu;
    float var = warp_sum(a0*a0 + a1*a1) * (1.0f/64.0f);
    float rs = rsqrtf(var + EPS);
    g_y[warp*DD + lane]      = a0*rs*l1g[lane]    + l1b[lane];
    g_y[warp*DD + lane + 32] = a1*rs*l1g[lane+32] + l1b[lane+32];
}

// ---------------- qkv GEMM: one N-tile per block (grid 941 x 3), tf32 --------
__global__ void __launch_bounds__(256, 3)
qkv_gemm(const float* __restrict__ A, const float* __restrict__ W,
         const float* __restrict__ bias, float* __restrict__ out) {
    __shared__ unsigned As[128*64];
    __shared__ unsigned Bs[64*64];
    int tid = threadIdx.x;
    int warp = tid >> 5, lane = tid & 31;
    int wm = warp >> 1, wn = warp & 1;
    int row0 = blockIdx.x * 128;
    int nt = blockIdx.y;
    int qr = lane >> 2, qk = lane & 3;

    #pragma unroll
    for (int i = 0; i < 8; i++) {
        int idx = tid + i*256;
        int r = idx >> 4, c4 = (idx & 15) << 2;
        int gr = row0 + r;
        float4 v = (gr < MROWS) ? *(const float4*)(A + (size_t)gr*64 + c4)
                                : make_float4(0.f,0.f,0.f,0.f);
        *(float4*)(&As[ASWI(r, c4)]) = v;
    }
    #pragma unroll
    for (int i = 0; i < 4; i++) {
        int idx = tid + i*256;
        int r = idx >> 4, c4 = (idx & 15) << 2;
        float4 v = *(const float4*)(W + (size_t)(nt*64 + r)*64 + c4);
        *(float4*)(&Bs[ASWI(r, c4)]) = v;
    }
    __syncthreads();

    float c[2][4][4];
    #pragma unroll
    for (int i = 0; i < 2; i++)
        #pragma unroll
        for (int j = 0; j < 4; j++)
            #pragma unroll
            for (int r = 0; r < 4; r++) c[i][j][r] = 0.f;

    #pragma unroll
    for (int kc = 0; kc < 8; kc++) {
        int kb = kc*8;
        unsigned a[2][4], b[4][2];
        #pragma unroll
        for (int i = 0; i < 2; i++) {
            int r = wm*32 + i*16 + qr;
            a[i][0] = As[ASWI(r,     kb + qk)];
            a[i][1] = As[ASWI(r + 8, kb + qk)];
            a[i][2] = As[ASWI(r,     kb + qk + 4)];
            a[i][3] = As[ASWI(r + 8, kb + qk + 4)];
        }
        #pragma unroll
        for (int j = 0; j < 4; j++) {
            int nn = wn*32 + j*8 + qr;
            b[j][0] = Bs[ASWI(nn, kb + qk)];
            b[j][1] = Bs[ASWI(nn, kb + qk + 4)];
        }
        #pragma unroll
        for (int i = 0; i < 2; i++)
            #pragma unroll
            for (int j = 0; j < 4; j++)
                mma_tf32(c[i][j][0], c[i][j][1], c[i][j][2], c[i][j][3],
                         a[i][0], a[i][1], a[i][2], a[i][3], b[j][0], b[j][1]);
    }

    #pragma unroll
    for (int i = 0; i < 2; i++) {
        #pragma unroll
        for (int half = 0; half < 2; half++) {
            int gr = row0 + wm*32 + i*16 + qr + half*8;
            if (gr >= MROWS) continue;
            #pragma unroll
            for (int j = 0; j < 4; j++) {
                int gc = nt*64 + wn*32 + j*8 + qk*2;
                float v0 = c[i][half*2]     [j*0] ; // placeholder avoided below
                (void)v0;
                float w0 = c[i][j][half*2]     + bias[gc];
                float w1 = c[i][j][half*2 + 1] + bias[gc + 1];
                *(float2*)(out + (size_t)gr*192 + gc) = make_float2(w0, w1);
            }
        }
    }
}

// ---------------- fused half layer: bf16 operands, fp32 accum/residual -------
// Abuf/Zbuf/Wbuf: 64x32 packed bf16-pair words (8KB each); Hbuf fp32 (16.9KB)
#define HSM_A 0
#define HSM_Z 8192
#define HSM_W 16384
#define HSM_H 24576
#define HSM_TOTAL 41472   // 24576 + 64*66*4

__global__ void __launch_bounds__(256, 3)
half_layer(const float* __restrict__ o,
           const float* __restrict__ Wout, const float* __restrict__ bout,
           float* __restrict__ h,
           const float* __restrict__ ln2g, const float* __restrict__ ln2b,
           const float* __restrict__ W1, const float* __restrict__ b1,
           const float* __restrict__ W2, const float* __restrict__ b2,
           const float* __restrict__ ln1g, const float* __restrict__ ln1b,
           float* __restrict__ y) {
    extern __shared__ __align__(16) char sm[];
    unsigned* Abuf = (unsigned*)(sm + HSM_A);   // 64x32 pair-words
    unsigned* Zbuf = (unsigned*)(sm + HSM_Z);   // 64x32 pair-words
    unsigned* Wbuf = (unsigned*)(sm + HSM_W);   // 64x32 pair-words
    float*    Hbuf = (float*)(sm + HSM_H);      // 64 x stride 66, fp32

    int tid = threadIdx.x;
    int warp = tid >> 5, lane = tid & 31;
    int wm = warp >> 1, wn = warp & 1;
    int row0 = blockIdx.x * 64;
    int qr = lane >> 2, qk = lane & 3;
    int rlo = wm*16 + qr, rhi = rlo + 8;
    int grlo = row0 + rlo, grhi = row0 + rhi;

    // ---- stage o + Wout as bf16 pairs ----
    #pragma unroll
    for (int i = 0; i < 4; i++) {
        int idx = tid + i*256;
        int r = idx >> 4, cp = (idx & 15) << 1;   // pair col base (2 pairs)
        int gr = row0 + r;
        float4 v = (gr < MROWS) ? *(const float4*)(o + (size_t)gr*64 + 2*cp)
                                : make_float4(0.f,0.f,0.f,0.f);
        *(uint2*)(&Abuf[ASW2(r, cp)]) =
            make_uint2(pk_bf16(v.x, v.y), pk_bf16(v.z, v.w));
        float4 w = *(const float4*)(Wout + (size_t)r*64 + 2*cp);
        *(uint2*)(&Wbuf[ASW2(r, cp)]) =
            make_uint2(pk_bf16(w.x, w.y), pk_bf16(w.z, w.w));
    }
    __syncthreads();

    // ---- out-proj mma (bf16 k16) -> residual into Hbuf ----
    {
        float c[4][4];
        #pragma unroll
        for (int j = 0; j < 4; j++)
            #pragma unroll
            for (int r = 0; r < 4; r++) c[j][r] = 0.f;
        #pragma unroll
        for (int kc = 0; kc < 4; kc++) {
            int kb2 = kc*8;
            unsigned a0 = Abuf[ASW2(rlo, kb2 + qk)];
            unsigned a1 = Abuf[ASW2(rhi, kb2 + qk)];
            unsigned a2 = Abuf[ASW2(rlo, kb2 + qk + 4)];
            unsigned a3 = Abuf[ASW2(rhi, kb2 + qk + 4)];
            #pragma unroll
            for (int j = 0; j < 4; j++) {
                int nn = wn*32 + j*8 + qr;
                mma_bf16_k16(c[j][0], c[j][1], c[j][2], c[j][3],
                             a0, a1, a2, a3,
                             Wbuf[ASW2(nn, kb2 + qk)], Wbuf[ASW2(nn, kb2 + qk + 4)]);
            }
        }
        #pragma unroll
        for (int j = 0; j < 4; j++) {
            int gc = wn*32 + j*8 + 2*qk;
            float hv0 = c[j][0] + bout[gc], hv1 = c[j][1] + bout[gc+1];
            float hv2 = c[j][2] + bout[gc], hv3 = c[j][3] + bout[gc+1];
            if (grlo < MROWS) { float2 t = *(const float2*)(h + (size_t)grlo*64 + gc); hv0 += t.x; hv1 += t.y; }
            if (grhi < MROWS) { float2 t = *(const float2*)(h + (size_t)grhi*64 + gc); hv2 += t.x; hv3 += t.y; }
            *(float2*)(&Hbuf[rlo*66 + gc]) = make_float2(hv0, hv1);
            *(float2*)(&Hbuf[rhi*66 + gc]) = make_float2(hv2, hv3);
        }
    }
    __syncthreads();

    // ---- LN2 -> y2 (bf16 pairs) into Abuf ----
    for (int rr = warp; rr < 64; rr += 8) {
        float2 v = *(float2*)(&Hbuf[rr*66 + 2*lane]);
        float mu = warp_sum(v.x + v.y) * (1.0f/64.0f);
        float a0 = v.x - mu, a1 = v.y - mu;
        float var = warp_sum(a0*a0 + a1*a1) * (1.0f/64.0f);
        float rs = rsqrtf(var + EPS);
        float2 gg = ((const float2*)ln2g)[lane];
        float2 bb = ((const float2*)ln2b)[lane];
        Abuf[ASW2(rr, lane)] = pk_bf16(a0*rs*gg.x + bb.x, a1*rs*gg.y + bb.y);
    }
    __syncthreads();

    // ---- FF: z stays in smem (bf16) ----
    float d[4][4];
    #pragma unroll
    for (int j = 0; j < 4; j++)
        #pragma unroll
        for (int r = 0; r < 4; r++) d[j][r] = 0.f;

    for (int t = 0; t < 4; t++) {
        #pragma unroll
        for (int i = 0; i < 4; i++) {
            int idx = tid + i*256;
            int r = idx >> 4, cp = (idx & 15) << 1;
            float4 w = *(const float4*)(W1 + (size_t)(t*64 + r)*64 + 2*cp);
            *(uint2*)(&Wbuf[ASW2(r, cp)]) =
                make_uint2(pk_bf16(w.x, w.y), pk_bf16(w.z, w.w));
        }
        __syncthreads();

        float zc[4][4];
        #pragma unroll
        for (int j = 0; j < 4; j++)
            #pragma unroll
            for (int r = 0; r < 4; r++) zc[j][r] = 0.f;
        #pragma unroll
        for (int kc = 0; kc < 4; kc++) {
            int kb2 = kc*8;
            unsigned a0 = Abuf[ASW2(rlo, kb2 + qk)];
            unsigned a1 = Abuf[ASW2(rhi, kb2 + qk)];
            unsigned a2 = Abuf[ASW2(rlo, kb2 + qk + 4)];
            unsigned a3 = Abuf[ASW2(rhi, kb2 + qk + 4)];
            #pragma unroll
            for (int j = 0; j < 4; j++) {
                int nn = wn*32 + j*8 + qr;
                mma_bf16_k16(zc[j][0], zc[j][1], zc[j][2], zc[j][3],
                             a0, a1, a2, a3,
                             Wbuf[ASW2(nn, kb2 + qk)], Wbuf[ASW2(nn, kb2 + qk + 4)]);
            }
        }
        #pragma unroll
        for (int j = 0; j < 4; j++) {
            int gc = t*64 + wn*32 + j*8 + 2*qk;
            int pp = wn*16 + j*4 + qk;   // pair column
            float z0 = gelu_exact(zc[j][0] + b1[gc]);
            float z1 = gelu_exact(zc[j][1] + b1[gc+1]);
            float z2 = gelu_exact(zc[j][2] + b1[gc]);
            float z3 = gelu_exact(zc[j][3] + b1[gc+1]);
            Zbuf[ASW2(rlo, pp)] = pk_bf16(z0, z1);
            Zbuf[ASW2(rhi, pp)] = pk_bf16(z2, z3);
        }
        __syncthreads();

        #pragma unroll
        for (int i = 0; i < 4; i++) {
            int idx = tid + i*256;
            int r = idx >> 4, cp = (idx & 15) << 1;
            float4 w = *(const float4*)(W2 + (size_t)r*256 + t*64 + 2*cp);
            *(uint2*)(&Wbuf[ASW2(r, cp)]) =
                make_uint2(pk_bf16(w.x, w.y), pk_bf16(w.z, w.w));
        }
        __syncthreads();

        #pragma unroll
        for (int kc = 0; kc < 4; kc++) {
            int kb2 = kc*8;
            unsigned a0 = Zbuf[ASW2(rlo, kb2 + qk)];
            unsigned a1 = Zbuf[ASW2(rhi, kb2 + qk)];
            unsigned a2 = Zbuf[ASW2(rlo, kb2 + qk + 4)];
            unsigned a3 = Zbuf[ASW2(rhi, kb2 + qk + 4)];
            #pragma unroll
            for (int j = 0; j < 4; j++) {
                int nn = wn*32 + j*8 + qr;
                mma_bf16_k16(d[j][0], d[j][1], d[j][2], d[j][3],
                             a0, a1, a2, a3,
                             Wbuf[ASW2(nn, kb2 + qk)], Wbuf[ASW2(nn, kb2 + qk + 4)]);
            }
        }
        __syncthreads();
    }

    // ---- epilogue: hn = h' + ff2out ----
    #pragma unroll
    for (int j = 0; j < 4; j++) {
        int gc = wn*32 + j*8 + 2*qk;
        float2 hlo = *(float2*)(&Hbuf[rlo*66 + gc]);
        float2 hhi = *(float2*)(&Hbuf[rhi*66 + gc]);
        float v0 = d[j][0] + b2[gc]   + hlo.x;
        float v1 = d[j][1] + b2[gc+1] + hlo.y;
        float v2 = d[j][2] + b2[gc]   + hhi.x;
        float v3 = d[j][3] + b2[gc+1] + hhi.y;
        if (grlo < MROWS) *(float2*)(h + (size_t)grlo*64 + gc) = make_float2(v0, v1);
        if (grhi < MROWS) *(float2*)(h + (size_t)grhi*64 + gc) = make_float2(v2, v3);
        *(float2*)(&Hbuf[rlo*66 + gc]) = make_float2(v0, v1);
        *(float2*)(&Hbuf[rhi*66 + gc]) = make_float2(v2, v3);
    }

    if (ln1g == nullptr) return;
    __syncthreads();

    for (int rr = warp; rr < 64; rr += 8) {
        int grow = row0 + rr;
        if (grow >= MROWS) break;
        float2 v = *(float2*)(&Hbuf[rr*66 + 2*lane]);
        float mu = warp_sum(v.x + v.y) * (1.0f/64.0f);
        float a0 = v.x - mu, a1 = v.y - mu;
        float var = warp_sum(a0*a0 + a1*a1) * (1.0f/64.0f);
        float rs = rsqrtf(var + EPS);
        float2 gg = ((const float2*)ln1g)[lane];
        float2 bb = ((const float2*)ln1b)[lane];
        ((float2*)(y + (size_t)grow*64))[lane] =
            make_float2(a0*rs*gg.x + bb.x, a1*rs*gg.y + bb.y);
    }
}

// ---------------- bf16 flash attention (zero-shuffle P remap) ----------------
#define VROW 156   // 312 keys as bf16 pairs; stride 156 words

__global__ void __launch_bounds__(320) attn_kernel(const float* __restrict__ qkv,
                                                   float* __restrict__ o) {
    __shared__ unsigned Kb[304*4];   // K[key][d] bf16 pairs
    __shared__ unsigned Vt[8*VROW];  // V^T[d][key] bf16 pairs
    int n = blockIdx.x >> 3;
    int h = blockIdx.x & 7;
    int tid = threadIdx.x, warp = tid >> 5, lane = tid & 31;
    int gr = lane >> 2, qk = lane & 3;
    const float* base = qkv + (size_t)n*SS*(3*DD) + h*HD;

    for (int i = tid; i < 304*4; i += 320) {
        int s = i >> 2, dp = i & 3;
        float k0 = 0.f, k1 = 0.f;
        if (s < SS) {
            const float* rp = base + (size_t)s*(3*DD) + DD + 2*dp;
            k0 = rp[0]; k1 = rp[1];
        }
        Kb[i] = pk_bf16(k0, k1);
    }
    for (int i = tid; i < 8*152; i += 320) {
        int d = i / 152, kp = i % 152;
        int s0 = 2*kp, s1 = 2*kp + 1;
        float v0 = (s0 < SS) ? base[(size_t)s0*(3*DD) + 2*DD + d] : 0.f;
        float v1 = (s1 < SS) ? base[(size_t)s1*(3*DD) + 2*DD + d] : 0.f;
        Vt[d*VROW + kp] = pk_bf16(v0, v1);
    }
    __syncthreads();

    const float sc = 0.35355339059327373f * 1.4426950408889634f; // 1/sqrt(8)*log2e

    for (int tile = warp; tile < 19; tile += 10) {
        int q0 = tile*16;
        int r0 = min(q0 + gr, SS-1);
        int r1 = min(q0 + gr + 8, SS-1);
        const float* qp0 = base + (size_t)r0*(3*DD) + 2*qk;
        const float* qp1 = base + (size_t)r1*(3*DD) + 2*qk;
        unsigned qa0 = pk_bf16(qp0[0]*sc, qp0[1]*sc);
        unsigned qa1 = pk_bf16(qp1[0]*sc, qp1[1]*sc);

        float o0=0.f, o1=0.f, o2=0.f, o3=0.f;
        float l0=0.f, l1=0.f;

        #pragma unroll 2
        for (int kt = 0; kt < 19; kt++) {
            int kb = kt*16;
            unsigned b0 = Kb[(kb + gr)*4 + qk];
            unsigned b1 = Kb[(kb + 8 + gr)*4 + qk];
            float c0=0.f, c1=0.f, c2=0.f, c3=0.f;
            float e0=0.f, e1=0.f, e2=0.f, e3=0.f;
            mma_bf16_k8(c0, c1, c2, c3, qa0, qa1, b0);
            mma_bf16_k8(e0, e1, e2, e3, qa0, qa1, b1);

            float p0, p1, p2, p3, s0, s1, s2, s3;
            asm("ex2.approx.f32 %0, %1;" : "=f"(p0) : "f"(c0));
            asm("ex2.approx.f32 %0, %1;" : "=f"(p1) : "f"(c1));
            asm("ex2.approx.f32 %0, %1;" : "=f"(p2) : "f"(c2));
            asm("ex2.approx.f32 %0, %1;" : "=f"(p3) : "f"(c3));
            asm("ex2.approx.f32 %0, %1;" : "=f"(s0) : "f"(e0));
            asm("ex2.approx.f32 %0, %1;" : "=f"(s1) : "f"(e1));
            asm("ex2.approx.f32 %0, %1;" : "=f"(s2) : "f"(e2));
            asm("ex2.approx.f32 %0, %1;" : "=f"(s3) : "f"(e3));
            if (kt == 18) {
                int k0i = kb + 8 + 2*qk;
                if (k0i     > 300) { s0 = 0.f; s2 = 0.f; }
                if (k0i + 1 > 300) { s1 = 0.f; s3 = 0.f; }
            }
            l0 += p0 + p1 + s0 + s1;
            l1 += p2 + p3 + s2 + s3;

            unsigned pa0 = pk_bf16(p0, p1);
            unsigned pa1 = pk_bf16(p2, p3);
            unsigned pa2 = pk_bf16(s0, s1);
            unsigned pa3 = pk_bf16(s2, s3);

            unsigned vb0 = Vt[gr*VROW + (kb >> 1) + qk];
            unsigned vb1 = Vt[gr*VROW + (kb >> 1) + 4 + qk];
            mma_bf16_k16(o0, o1, o2, o3, pa0, pa1, pa2, pa3, vb0, vb1);
        }

        l0 += __shfl_xor_sync(0xffffffffu, l0, 1);
        l0 += __shfl_xor_sync(0xffffffffu, l0, 2);
        l1 += __shfl_xor_sync(0xffffffffu, l1, 1);
        l1 += __shfl_xor_sync(0xffffffffu, l1, 2);
        float inv0 = 1.0f / l0, inv1 = 1.0f / l1;

        int row0g = q0 + gr, row1g = q0 + gr + 8;
        if (row0g < SS)
            *(float2*)(o + ((size_t)n*SS + row0g)*DD + h*HD + 2*qk) =
                make_float2(o0*inv0, o1*inv0);
        if (row1g < SS)
            *(float2*)(o + ((size_t)n*SS + row1g)*DD + h*HD + 2*qk) =
                make_float2(o2*inv1, o3*inv1);
    }
}

// ---------------- cls pool over edges + LayerNorm ----------------------------
__global__ void pool_kernel(const float* __restrict__ g, const float* __restrict__ bt) {
    int warp = threadIdx.x >> 5;
    int lane = threadIdx.x & 31;
    if (warp >= BB) return;
    int b = warp;
    float v0 = 0.f, v1 = 0.f;
    for (int e = 0; e < EE; e++) {
        size_t base = ((size_t)(b*EE + e)*SS)*DD;
        v0 += g_h[base + lane];
        v1 += g_h[base + lane + 32];
    }
    v0 *= (1.0f/EE); v1 *= (1.0f/EE);
    float mu = warp_sum(v0 + v1) * (1.0f/64.0f);
    float a0 = v0 - mu, a1 = v1 - mu;
    float var = warp_sum(a0*a0 + a1*a1) * (1.0f/64.0f);
    float rs = rsqrtf(var + EPS);
    g_feat[b*DD + lane]    = a0*rs*g[lane]    + bt[lane];
    g_feat[b*DD + lane+32] = a1*rs*g[lane+32] + bt[lane+32];
}

// ---------------- head MLP ---------------------------------------------------
__global__ void head1_kernel(const float* __restrict__ w, const float* __restrict__ bias) {
    __shared__ float f[DD];
    int b = blockIdx.x, d = threadIdx.x;
    f[d] = g_feat[b*DD + d];
    __syncthreads();
    float acc = bias[d];
    #pragma unroll 8
    for (int k = 0; k < DD; k++) acc = fmaf(f[k], w[d*DD + k], acc);
    g_feat2[b*DD + d] = gelu_exact(acc);
}

__global__ void head2_kernel(const float* __restrict__ w, const float* __restrict__ bias,
                             float* __restrict__ out) {
    __shared__ float f[DD];
    int b = blockIdx.x, c = threadIdx.x;
    f[c] = g_feat2[b*DD + c];
    __syncthreads();
    if (c >= NCLS) return;
    float acc = bias[c];
    #pragma unroll 8
    for (int k = 0; k < DD; k++) acc = fmaf(f[k], w[c*DD + k], acc);
    out[b*NCLS + c] = acc;
}

// ---------------- launcher ---------------------------------------------------
extern "C" void kernel_launch(void* const* d_in, const int* in_sizes, int n_in,
                              void* d_out, int out_size) {
    const float* x       = (const float*)d_in[0];
    const float* embed_w = (const float*)d_in[1];
    const float* embed_b = (const float*)d_in[2];
    const float* eln_g   = (const float*)d_in[3];
    const float* eln_b   = (const float*)d_in[4];
    const float* cls     = (const float*)d_in[5];
    const float* qkv_w   = (const float*)d_in[6];
    const float* qkv_b   = (const float*)d_in[7];
    const float* out_w   = (const float*)d_in[8];
    const float* out_b   = (const float*)d_in[9];
    const float* ln1_g   = (const float*)d_in[10];
    const float* ln1_b   = (const float*)d_in[11];
    const float* ln2_g   = (const float*)d_in[12];
    const float* ln2_b   = (const float*)d_in[13];
    const float* ff1_w   = (const float*)d_in[14];
    const float* ff1_b   = (const float*)d_in[15];
    const float* ff2_w   = (const float*)d_in[16];
    const float* ff2_b   = (const float*)d_in[17];
    const float* norm_g  = (const float*)d_in[18];
    const float* norm_b  = (const float*)d_in[19];
    const float* h1_w    = (const float*)d_in[20];
    const float* h1_b    = (const float*)d_in[21];
    const float* h2_w    = (const float*)d_in[22];
    const float* h2_b    = (const float*)d_in[23];
    float* out = (float*)d_out;

    float *hbuf, *ybuf, *qkvbuf, *obuf;
    cudaGetSymbolAddress((void**)&hbuf,   g_h);
    cudaGetSymbolAddress((void**)&ybuf,   g_y);
    cudaGetSymbolAddress((void**)&qkvbuf, g_qkv);
    cudaGetSymbolAddress((void**)&obuf,   g_o);

    cudaFuncSetAttribute(half_layer,
                         cudaFuncAttributeMaxDynamicSharedMemorySize, HSM_TOTAL);

    const int rows_grid = (MROWS + 7) / 8;
    const int gm128 = (MROWS + 127) / 128;  // 941
    const int gm64  = (MROWS + 63) / 64;    // 1882

    embed_kernel<<<rows_grid, 256>>>(x, embed_w, embed_b, eln_g, eln_b, cls,
                                     ln1_g, ln1_b);

    for (int l = 0; l < LL; l++) {
        qkv_gemm<<<dim3(gm128, 3), 256>>>(ybuf, qkv_w + (size_t)l*3*DD*DD,
                                          qkv_b + l*3*DD, qkvbuf);
        attn_kernel<<<NN*HH, 320>>>(qkvbuf, obuf);
        const float* nlg = (l < LL-1) ? (ln1_g + (l+1)*DD) : nullptr;
        const float* nlb = (l < LL-1) ? (ln1_b + (l+1)*DD) : nullptr;
        half_layer<<<gm64, 256, HSM_TOTAL>>>(
            obuf, out_w + (size_t)l*DD*DD, out_b + l*DD,
            hbuf, ln2_g + l*DD, ln2_b + l*DD,
            ff1_w + (size_t)l*FFD*DD, ff1_b + l*FFD,
            ff2_w + (size_t)l*DD*FFD, ff2_b + l*DD,
            nlg, nlb, ybuf);
    }

    pool_kernel<<<1, 512>>>(norm_g, norm_b);
    head1_kernel<<<BB, DD>>>(h1_w, h1_b);
    head2_kernel<<<BB, DD>>>(h2_w, h2_b, out);
}

// round 15
// speedup vs baseline: 1.5605x; 1.0305x over previous
#include <cuda_runtime.h>
#include <cuda_bf16.h>
#include <math.h>

// Problem constants
#define BB 16
#define EE 25
#define TT 300
#define CC 3
#define DD 64
#define HH 8
#define FFD 256
#define LL 4
#define NCLS 60
#define NN (BB*EE)        // 400
#define SS (TT+1)         // 301
#define HD (DD/HH)        // 8
#define MROWS (NN*SS)     // 120400
#define EPS 1e-5f

// ---------------- scratch buffers -------------------------------------------
__device__ float g_h[MROWS*DD];      // residual stream
__device__ float g_y[MROWS*DD];      // LN output
__device__ float g_qkv[MROWS*3*DD];  // qkv
__device__ float g_o[MROWS*DD];      // attention output
__device__ float g_pe[SS*DD];        // positional encoding table
__device__ float g_feat[BB*DD];
__device__ float g_feat2[BB*DD];

// ---------------- helpers ---------------------------------------------------
__device__ __forceinline__ float warp_sum(float v) {
    #pragma unroll
    for (int o = 16; o; o >>= 1) v += __shfl_xor_sync(0xffffffffu, v, o);
    return v;
}

__device__ __forceinline__ float gelu_exact(float x) {
    return 0.5f * x * (1.0f + erff(x * 0.70710678118654752f));
}

// pack two f32 -> bf16x2 (lo = first arg)
__device__ __forceinline__ unsigned pk_bf16(float lo, float hi) {
    unsigned r;
    asm("cvt.rn.bf16x2.f32 %0, %1, %2;" : "=r"(r) : "f"(hi), "f"(lo));
    return r;
}

__device__ __forceinline__ void mma_bf16_k8(float& c0, float& c1, float& c2, float& c3,
                                            unsigned a0, unsigned a1, unsigned b0) {
    asm volatile(
        "mma.sync.aligned.m16n8k8.row.col.f32.bf16.bf16.f32 "
        "{%0,%1,%2,%3}, {%4,%5}, {%6}, {%0,%1,%2,%3};"
        : "+f"(c0), "+f"(c1), "+f"(c2), "+f"(c3)
        : "r"(a0), "r"(a1), "r"(b0));
}

__device__ __forceinline__ void mma_bf16_k16(float& c0, float& c1, float& c2, float& c3,
                                             unsigned a0, unsigned a1, unsigned a2, unsigned a3,
                                             unsigned b0, unsigned b1) {
    asm volatile(
        "mma.sync.aligned.m16n8k16.row.col.f32.bf16.bf16.f32 "
        "{%0,%1,%2,%3}, {%4,%5,%6,%7}, {%8,%9}, {%0,%1,%2,%3};"
        : "+f"(c0), "+f"(c1), "+f"(c2), "+f"(c3)
        : "r"(a0), "r"(a1), "r"(a2), "r"(a3), "r"(b0), "r"(b1));
}

// bf16-pair tiles: 32 words per row
#define ASW2(r,c) ((r)*32 + (((c) ^ (((r)&7)<<2))))

// ---------------- positional-encoding table ----------------------------------
__global__ void pe_kernel() {
    int s = blockIdx.x, d = threadIdx.x;
    const float kfreq = -0.14391565f; // -ln(10000)/64
    int i = d >> 1;
    float ang = (float)s * __expf((float)(2*i) * kfreq);
    g_pe[s*DD + d] = (d & 1) ? cosf(ang) : sinf(ang);
}

// ---------------- embed + LN + cls + pos + fused ln1[0] ----------------------
__global__ void embed_kernel(const float* __restrict__ x,
                             const float* __restrict__ ew,
                             const float* __restrict__ ebias,
                             const float* __restrict__ eg,
                             const float* __restrict__ ebt,
                             const float* __restrict__ cls,
                             const float* __restrict__ l1g,
                             const float* __restrict__ l1b) {
    int warp = (blockIdx.x * blockDim.x + threadIdx.x) >> 5;
    int lane = threadIdx.x & 31;
    if (warp >= MROWS) return;
    int n = warp / SS, s = warp % SS;
    int b = n / EE, e = n % EE;

    float v0, v1;
    if (s == 0) {
        v0 = cls[lane];
        v1 = cls[lane + 32];
    } else {
        int t = s - 1;
        float x0 = x[((b*CC + 0)*TT + t)*EE + e];
        float x1 = x[((b*CC + 1)*TT + t)*EE + e];
        float x2 = x[((b*CC + 2)*TT + t)*EE + e];
        int d0 = lane, d1 = lane + 32;
        v0 = ebias[d0] + x0*ew[d0*3] + x1*ew[d0*3+1] + x2*ew[d0*3+2];
        v1 = ebias[d1] + x0*ew[d1*3] + x1*ew[d1*3+1] + x2*ew[d1*3+2];
        float mu = warp_sum(v0 + v1) * (1.0f/64.0f);
        float a0 = v0 - mu, a1 = v1 - mu;
        float var = warp_sum(a0*a0 + a1*a1) * (1.0f/64.0f);
        float r = rsqrtf(var + EPS);
        v0 = a0 * r * eg[d0] + ebt[d0];
        v1 = a1 * r * eg[d1] + ebt[d1];
    }
    v0 += g_pe[s*DD + lane];
    v1 += g_pe[s*DD + lane + 32];

    g_h[warp*DD + lane]      = v0;
    g_h[warp*DD + lane + 32] = v1;
    // fused ln1[0]
    float mu = warp_sum(v0 + v1) * (1.0f/64.0f);
    float a0 = v0 - mu, a1 = v1 - mu;
    float var = warp_sum(a0*a0 + a1*a1) * (1.0f/64.0f);
    float rs = rsqrtf(var + EPS);
    g_y[warp*DD + lane]      = a0*rs*l1g[lane]    + l1b[lane];
    g_y[warp*DD + lane + 32] = a1*rs*l1g[lane+32] + l1b[lane+32];
}

// ---------------- qkv GEMM: bf16 k16, one N-tile per block (941 x 3) ---------
__global__ void __launch_bounds__(256, 3)
qkv_gemm(const float* __restrict__ A, const float* __restrict__ W,
         const float* __restrict__ bias, float* __restrict__ out) {
    __shared__ unsigned As[128*32];   // 16KB: 128 rows x 32 pair-words
    __shared__ unsigned Bs[64*32];    // 8KB
    int tid = threadIdx.x;
    int warp = tid >> 5, lane = tid & 31;
    int wm = warp >> 1, wn = warp & 1;
    int row0 = blockIdx.x * 128;
    int nt = blockIdx.y;
    int qr = lane >> 2, qk = lane & 3;

    #pragma unroll
    for (int i = 0; i < 8; i++) {
        int idx = tid + i*256;
        int r = idx >> 4, cp = (idx & 15) << 1;
        int gr = row0 + r;
        float4 v = (gr < MROWS) ? *(const float4*)(A + (size_t)gr*64 + 2*cp)
                                : make_float4(0.f,0.f,0.f,0.f);
        *(uint2*)(&As[ASW2(r, cp)]) =
            make_uint2(pk_bf16(v.x, v.y), pk_bf16(v.z, v.w));
    }
    #pragma unroll
    for (int i = 0; i < 4; i++) {
        int idx = tid + i*256;
        int r = idx >> 4, cp = (idx & 15) << 1;
        float4 v = *(const float4*)(W + (size_t)(nt*64 + r)*64 + 2*cp);
        *(uint2*)(&Bs[ASW2(r, cp)]) =
            make_uint2(pk_bf16(v.x, v.y), pk_bf16(v.z, v.w));
    }
    __syncthreads();

    float c[2][4][4];
    #pragma unroll
    for (int i = 0; i < 2; i++)
        #pragma unroll
        for (int j = 0; j < 4; j++)
            #pragma unroll
            for (int r = 0; r < 4; r++) c[i][j][r] = 0.f;

    #pragma unroll
    for (int kc = 0; kc < 4; kc++) {
        int kb2 = kc*8;
        unsigned a[2][4], b[4][2];
        #pragma unroll
        for (int i = 0; i < 2; i++) {
            int r = wm*32 + i*16 + qr;
            a[i][0] = As[ASW2(r,     kb2 + qk)];
            a[i][1] = As[ASW2(r + 8, kb2 + qk)];
            a[i][2] = As[ASW2(r,     kb2 + qk + 4)];
            a[i][3] = As[ASW2(r + 8, kb2 + qk + 4)];
        }
        #pragma unroll
        for (int j = 0; j < 4; j++) {
            int nn = wn*32 + j*8 + qr;
            b[j][0] = Bs[ASW2(nn, kb2 + qk)];
            b[j][1] = Bs[ASW2(nn, kb2 + qk + 4)];
        }
        #pragma unroll
        for (int i = 0; i < 2; i++)
            #pragma unroll
            for (int j = 0; j < 4; j++)
                mma_bf16_k16(c[i][j][0], c[i][j][1], c[i][j][2], c[i][j][3],
                             a[i][0], a[i][1], a[i][2], a[i][3], b[j][0], b[j][1]);
    }

    #pragma unroll
    for (int i = 0; i < 2; i++) {
        #pragma unroll
        for (int half = 0; half < 2; half++) {
            int gr = row0 + wm*32 + i*16 + qr + half*8;
            if (gr >= MROWS) continue;
            #pragma unroll
            for (int j = 0; j < 4; j++) {
                int gc = nt*64 + wn*32 + j*8 + qk*2;
                float w0 = c[i][j][half*2]     + bias[gc];
                float w1 = c[i][j][half*2 + 1] + bias[gc + 1];
                *(float2*)(out + (size_t)gr*192 + gc) = make_float2(w0, w1);
            }
        }
    }
}

// ---------------- fused half layer: bf16 operands, fp32 accum/residual -------
#define HSM_A 0
#define HSM_Z 8192
#define HSM_W 16384
#define HSM_H 24576
#define HSM_TOTAL 41472   // 24576 + 64*66*4

__global__ void __launch_bounds__(256, 3)
half_layer(const float* __restrict__ o,
           const float* __restrict__ Wout, const float* __restrict__ bout,
           float* __restrict__ h,
           const float* __restrict__ ln2g, const float* __restrict__ ln2b,
           const float* __restrict__ W1, const float* __restrict__ b1,
           const float* __restrict__ W2, const float* __restrict__ b2,
           const float* __restrict__ ln1g, const float* __restrict__ ln1b,
           float* __restrict__ y) {
    extern __shared__ __align__(16) char sm[];
    unsigned* Abuf = (unsigned*)(sm + HSM_A);   // 64x32 pair-words
    unsigned* Zbuf = (unsigned*)(sm + HSM_Z);   // 64x32 pair-words
    unsigned* Wbuf = (unsigned*)(sm + HSM_W);   // 64x32 pair-words
    float*    Hbuf = (float*)(sm + HSM_H);      // 64 x stride 66, fp32

    int tid = threadIdx.x;
    int warp = tid >> 5, lane = tid & 31;
    int wm = warp >> 1, wn = warp & 1;
    int row0 = blockIdx.x * 64;
    int qr = lane >> 2, qk = lane & 3;
    int rlo = wm*16 + qr, rhi = rlo + 8;
    int grlo = row0 + rlo, grhi = row0 + rhi;

    // ---- stage o + Wout as bf16 pairs ----
    #pragma unroll
    for (int i = 0; i < 4; i++) {
        int idx = tid + i*256;
        int r = idx >> 4, cp = (idx & 15) << 1;
        int gr = row0 + r;
        float4 v = (gr < MROWS) ? *(const float4*)(o + (size_t)gr*64 + 2*cp)
                                : make_float4(0.f,0.f,0.f,0.f);
        *(uint2*)(&Abuf[ASW2(r, cp)]) =
            make_uint2(pk_bf16(v.x, v.y), pk_bf16(v.z, v.w));
        float4 w = *(const float4*)(Wout + (size_t)r*64 + 2*cp);
        *(uint2*)(&Wbuf[ASW2(r, cp)]) =
            make_uint2(pk_bf16(w.x, w.y), pk_bf16(w.z, w.w));
    }
    __syncthreads();

    // ---- out-proj mma (bf16 k16) -> residual into Hbuf ----
    {
        float c[4][4];
        #pragma unroll
        for (int j = 0; j < 4; j++)
            #pragma unroll
            for (int r = 0; r < 4; r++) c[j][r] = 0.f;
        #pragma unroll
        for (int kc = 0; kc < 4; kc++) {
            int kb2 = kc*8;
            unsigned a0 = Abuf[ASW2(rlo, kb2 + qk)];
            unsigned a1 = Abuf[ASW2(rhi, kb2 + qk)];
            unsigned a2 = Abuf[ASW2(rlo, kb2 + qk + 4)];
            unsigned a3 = Abuf[ASW2(rhi, kb2 + qk + 4)];
            #pragma unroll
            for (int j = 0; j < 4; j++) {
                int nn = wn*32 + j*8 + qr;
                mma_bf16_k16(c[j][0], c[j][1], c[j][2], c[j][3],
                             a0, a1, a2, a3,
                             Wbuf[ASW2(nn, kb2 + qk)], Wbuf[ASW2(nn, kb2 + qk + 4)]);
            }
        }
        #pragma unroll
        for (int j = 0; j < 4; j++) {
            int gc = wn*32 + j*8 + 2*qk;
            float hv0 = c[j][0] + bout[gc], hv1 = c[j][1] + bout[gc+1];
            float hv2 = c[j][2] + bout[gc], hv3 = c[j][3] + bout[gc+1];
            if (grlo < MROWS) { float2 t = *(const float2*)(h + (size_t)grlo*64 + gc); hv0 += t.x; hv1 += t.y; }
            if (grhi < MROWS) { float2 t = *(const float2*)(h + (size_t)grhi*64 + gc); hv2 += t.x; hv3 += t.y; }
            *(float2*)(&Hbuf[rlo*66 + gc]) = make_float2(hv0, hv1);
            *(float2*)(&Hbuf[rhi*66 + gc]) = make_float2(hv2, hv3);
        }
    }
    __syncthreads();

    // ---- LN2 -> y2 (bf16 pairs) into Abuf ----
    for (int rr = warp; rr < 64; rr += 8) {
        float2 v = *(float2*)(&Hbuf[rr*66 + 2*lane]);
        float mu = warp_sum(v.x + v.y) * (1.0f/64.0f);
        float a0 = v.x - mu, a1 = v.y - mu;
        float var = warp_sum(a0*a0 + a1*a1) * (1.0f/64.0f);
        float rs = rsqrtf(var + EPS);
        float2 gg = ((const float2*)ln2g)[lane];
        float2 bb = ((const float2*)ln2b)[lane];
        Abuf[ASW2(rr, lane)] = pk_bf16(a0*rs*gg.x + bb.x, a1*rs*gg.y + bb.y);
    }
    __syncthreads();

    // ---- FF: z stays in smem (bf16) ----
    float d[4][4];
    #pragma unroll
    for (int j = 0; j < 4; j++)
        #pragma unroll
        for (int r = 0; r < 4; r++) d[j][r] = 0.f;

    for (int t = 0; t < 4; t++) {
        #pragma unroll
        for (int i = 0; i < 4; i++) {
            int idx = tid + i*256;
            int r = idx >> 4, cp = (idx & 15) << 1;
            float4 w = *(const float4*)(W1 + (size_t)(t*64 + r)*64 + 2*cp);
            *(uint2*)(&Wbuf[ASW2(r, cp)]) =
                make_uint2(pk_bf16(w.x, w.y), pk_bf16(w.z, w.w));
        }
        __syncthreads();

        float zc[4][4];
        #pragma unroll
        for (int j = 0; j < 4; j++)
            #pragma unroll
            for (int r = 0; r < 4; r++) zc[j][r] = 0.f;
        #pragma unroll
        for (int kc = 0; kc < 4; kc++) {
            int kb2 = kc*8;
            unsigned a0 = Abuf[ASW2(rlo, kb2 + qk)];
            unsigned a1 = Abuf[ASW2(rhi, kb2 + qk)];
            unsigned a2 = Abuf[ASW2(rlo, kb2 + qk + 4)];
            unsigned a3 = Abuf[ASW2(rhi, kb2 + qk + 4)];
            #pragma unroll
            for (int j = 0; j < 4; j++) {
                int nn = wn*32 + j*8 + qr;
                mma_bf16_k16(zc[j][0], zc[j][1], zc[j][2], zc[j][3],
                             a0, a1, a2, a3,
                             Wbuf[ASW2(nn, kb2 + qk)], Wbuf[ASW2(nn, kb2 + qk + 4)]);
            }
        }
        #pragma unroll
        for (int j = 0; j < 4; j++) {
            int gc = t*64 + wn*32 + j*8 + 2*qk;
            int pp = wn*16 + j*4 + qk;   // pair column
            float z0 = gelu_exact(zc[j][0] + b1[gc]);
            float z1 = gelu_exact(zc[j][1] + b1[gc+1]);
            float z2 = gelu_exact(zc[j][2] + b1[gc]);
            float z3 = gelu_exact(zc[j][3] + b1[gc+1]);
            Zbuf[ASW2(rlo, pp)] = pk_bf16(z0, z1);
            Zbuf[ASW2(rhi, pp)] = pk_bf16(z2, z3);
        }
        __syncthreads();

        #pragma unroll
        for (int i = 0; i < 4; i++) {
            int idx = tid + i*256;
            int r = idx >> 4, cp = (idx & 15) << 1;
            float4 w = *(const float4*)(W2 + (size_t)r*256 + t*64 + 2*cp);
            *(uint2*)(&Wbuf[ASW2(r, cp)]) =
                make_uint2(pk_bf16(w.x, w.y), pk_bf16(w.z, w.w));
        }
        __syncthreads();

        #pragma unroll
        for (int kc = 0; kc < 4; kc++) {
            int kb2 = kc*8;
            unsigned a0 = Zbuf[ASW2(rlo, kb2 + qk)];
            unsigned a1 = Zbuf[ASW2(rhi, kb2 + qk)];
            unsigned a2 = Zbuf[ASW2(rlo, kb2 + qk + 4)];
            unsigned a3 = Zbuf[ASW2(rhi, kb2 + qk + 4)];
            #pragma unroll
            for (int j = 0; j < 4; j++) {
                int nn = wn*32 + j*8 + qr;
                mma_bf16_k16(d[j][0], d[j][1], d[j][2], d[j][3],
                             a0, a1, a2, a3,
                             Wbuf[ASW2(nn, kb2 + qk)], Wbuf[ASW2(nn, kb2 + qk + 4)]);
            }
        }
        __syncthreads();
    }

    // ---- epilogue: hn = h' + ff2out ----
    #pragma unroll
    for (int j = 0; j < 4; j++) {
        int gc = wn*32 + j*8 + 2*qk;
        float2 hlo = *(float2*)(&Hbuf[rlo*66 + gc]);
        float2 hhi = *(float2*)(&Hbuf[rhi*66 + gc]);
        float v0 = d[j][0] + b2[gc]   + hlo.x;
        float v1 = d[j][1] + b2[gc+1] + hlo.y;
        float v2 = d[j][2] + b2[gc]   + hhi.x;
        float v3 = d[j][3] + b2[gc+1] + hhi.y;
        if (grlo < MROWS) *(float2*)(h + (size_t)grlo*64 + gc) = make_float2(v0, v1);
        if (grhi < MROWS) *(float2*)(h + (size_t)grhi*64 + gc) = make_float2(v2, v3);
        *(float2*)(&Hbuf[rlo*66 + gc]) = make_float2(v0, v1);
        *(float2*)(&Hbuf[rhi*66 + gc]) = make_float2(v2, v3);
    }

    if (ln1g == nullptr) return;
    __syncthreads();

    for (int rr = warp; rr < 64; rr += 8) {
        int grow = row0 + rr;
        if (grow >= MROWS) break;
        float2 v = *(float2*)(&Hbuf[rr*66 + 2*lane]);
        float mu = warp_sum(v.x + v.y) * (1.0f/64.0f);
        float a0 = v.x - mu, a1 = v.y - mu;
        float var = warp_sum(a0*a0 + a1*a1) * (1.0f/64.0f);
        float rs = rsqrtf(var + EPS);
        float2 gg = ((const float2*)ln1g)[lane];
        float2 bb = ((const float2*)ln1b)[lane];
        ((float2*)(y + (size_t)grow*64))[lane] =
            make_float2(a0*rs*gg.x + bb.x, a1*rs*gg.y + bb.y);
    }
}

// ---------------- bf16 flash attention (zero-shuffle P remap) ----------------
#define VROW 156   // 312 keys as bf16 pairs; stride 156 words

__global__ void __launch_bounds__(320) attn_kernel(const float* __restrict__ qkv,
                                                   float* __restrict__ o) {
    __shared__ unsigned Kb[304*4];   // K[key][d] bf16 pairs
    __shared__ unsigned Vt[8*VROW];  // V^T[d][key] bf16 pairs
    int n = blockIdx.x >> 3;
    int h = blockIdx.x & 7;
    int tid = threadIdx.x, warp = tid >> 5, lane = tid & 31;
    int gr = lane >> 2, qk = lane & 3;
    const float* base = qkv + (size_t)n*SS*(3*DD) + h*HD;

    for (int i = tid; i < 304*4; i += 320) {
        int s = i >> 2, dp = i & 3;
        float k0 = 0.f, k1 = 0.f;
        if (s < SS) {
            const float* rp = base + (size_t)s*(3*DD) + DD + 2*dp;
            k0 = rp[0]; k1 = rp[1];
        }
        Kb[i] = pk_bf16(k0, k1);
    }
    for (int i = tid; i < 8*152; i += 320) {
        int d = i / 152, kp = i % 152;
        int s0 = 2*kp, s1 = 2*kp + 1;
        float v0 = (s0 < SS) ? base[(size_t)s0*(3*DD) + 2*DD + d] : 0.f;
        float v1 = (s1 < SS) ? base[(size_t)s1*(3*DD) + 2*DD + d] : 0.f;
        Vt[d*VROW + kp] = pk_bf16(v0, v1);
    }
    __syncthreads();

    const float sc = 0.35355339059327373f * 1.4426950408889634f; // 1/sqrt(8)*log2e

    for (int tile = warp; tile < 19; tile += 10) {
        int q0 = tile*16;
        int r0 = min(q0 + gr, SS-1);
        int r1 = min(q0 + gr + 8, SS-1);
        const float* qp0 = base + (size_t)r0*(3*DD) + 2*qk;
        const float* qp1 = base + (size_t)r1*(3*DD) + 2*qk;
        unsigned qa0 = pk_bf16(qp0[0]*sc, qp0[1]*sc);
        unsigned qa1 = pk_bf16(qp1[0]*sc, qp1[1]*sc);

        float o0=0.f, o1=0.f, o2=0.f, o3=0.f;
        float l0=0.f, l1=0.f;

        #pragma unroll 2
        for (int kt = 0; kt < 19; kt++) {
            int kb = kt*16;
            unsigned b0 = Kb[(kb + gr)*4 + qk];
            unsigned b1 = Kb[(kb + 8 + gr)*4 + qk];
            float c0=0.f, c1=0.f, c2=0.f, c3=0.f;
            float e0=0.f, e1=0.f, e2=0.f, e3=0.f;
            mma_bf16_k8(c0, c1, c2, c3, qa0, qa1, b0);
            mma_bf16_k8(e0, e1, e2, e3, qa0, qa1, b1);

            float p0, p1, p2, p3, s0, s1, s2, s3;
            asm("ex2.approx.f32 %0, %1;" : "=f"(p0) : "f"(c0));
            asm("ex2.approx.f32 %0, %1;" : "=f"(p1) : "f"(c1));
            asm("ex2.approx.f32 %0, %1;" : "=f"(p2) : "f"(c2));
            asm("ex2.approx.f32 %0, %1;" : "=f"(p3) : "f"(c3));
            asm("ex2.approx.f32 %0, %1;" : "=f"(s0) : "f"(e0));
            asm("ex2.approx.f32 %0, %1;" : "=f"(s1) : "f"(e1));
            asm("ex2.approx.f32 %0, %1;" : "=f"(s2) : "f"(e2));
            asm("ex2.approx.f32 %0, %1;" : "=f"(s3) : "f"(e3));
            if (kt == 18) {
                int k0i = kb + 8 + 2*qk;
                if (k0i     > 300) { s0 = 0.f; s2 = 0.f; }
                if (k0i + 1 > 300) { s1 = 0.f; s3 = 0.f; }
            }
            l0 += p0 + p1 + s0 + s1;
            l1 += p2 + p3 + s2 + s3;

            unsigned pa0 = pk_bf16(p0, p1);
            unsigned pa1 = pk_bf16(p2, p3);
            unsigned pa2 = pk_bf16(s0, s1);
            unsigned pa3 = pk_bf16(s2, s3);

            unsigned vb0 = Vt[gr*VROW + (kb >> 1) + qk];
            unsigned vb1 = Vt[gr*VROW + (kb >> 1) + 4 + qk];
            mma_bf16_k16(o0, o1, o2, o3, pa0, pa1, pa2, pa3, vb0, vb1);
        }

        l0 += __shfl_xor_sync(0xffffffffu, l0, 1);
        l0 += __shfl_xor_sync(0xffffffffu, l0, 2);
        l1 += __shfl_xor_sync(0xffffffffu, l1, 1);
        l1 += __shfl_xor_sync(0xffffffffu, l1, 2);
        float inv0 = 1.0f / l0, inv1 = 1.0f / l1;

        int row0g = q0 + gr, row1g = q0 + gr + 8;
        if (row0g < SS)
            *(float2*)(o + ((size_t)n*SS + row0g)*DD + h*HD + 2*qk) =
                make_float2(o0*inv0, o1*inv0);
        if (row1g < SS)
            *(float2*)(o + ((size_t)n*SS + row1g)*DD + h*HD + 2*qk) =
                make_float2(o2*inv1, o3*inv1);
    }
}

// ---------------- cls pool over edges + LayerNorm ----------------------------
__global__ void pool_kernel(const float* __restrict__ g, const float* __restrict__ bt) {
    int warp = threadIdx.x >> 5;
    int lane = threadIdx.x & 31;
    if (warp >= BB) return;
    int b = warp;
    float v0 = 0.f, v1 = 0.f;
    for (int e = 0; e < EE; e++) {
        size_t base = ((size_t)(b*EE + e)*SS)*DD;
        v0 += g_h[base + lane];
        v1 += g_h[base + lane + 32];
    }
    v0 *= (1.0f/EE); v1 *= (1.0f/EE);
    float mu = warp_sum(v0 + v1) * (1.0f/64.0f);
    float a0 = v0 - mu, a1 = v1 - mu;
    float var = warp_sum(a0*a0 + a1*a1) * (1.0f/64.0f);
    float rs = rsqrtf(var + EPS);
    g_feat[b*DD + lane]    = a0*rs*g[lane]    + bt[lane];
    g_feat[b*DD + lane+32] = a1*rs*g[lane+32] + bt[lane+32];
}

// ---------------- head MLP ---------------------------------------------------
__global__ void head1_kernel(const float* __restrict__ w, const float* __restrict__ bias) {
    __shared__ float f[DD];
    int b = blockIdx.x, d = threadIdx.x;
    f[d] = g_feat[b*DD + d];
    __syncthreads();
    float acc = bias[d];
    #pragma unroll 8
    for (int k = 0; k < DD; k++) acc = fmaf(f[k], w[d*DD + k], acc);
    g_feat2[b*DD + d] = gelu_exact(acc);
}

__global__ void head2_kernel(const float* __restrict__ w, const float* __restrict__ bias,
                             float* __restrict__ out) {
    __shared__ float f[DD];
    int b = blockIdx.x, c = threadIdx.x;
    f[c] = g_feat2[b*DD + c];
    __syncthreads();
    if (c >= NCLS) return;
    float acc = bias[c];
    #pragma unroll 8
    for (int k = 0; k < DD; k++) acc = fmaf(f[k], w[c*DD + k], acc);
    out[b*NCLS + c] = acc;
}

// ---------------- launcher ---------------------------------------------------
extern "C" void kernel_launch(void* const* d_in, const int* in_sizes, int n_in,
                              void* d_out, int out_size) {
    const float* x       = (const float*)d_in[0];
    const float* embed_w = (const float*)d_in[1];
    const float* embed_b = (const float*)d_in[2];
    const float* eln_g   = (const float*)d_in[3];
    const float* eln_b   = (const float*)d_in[4];
    const float* cls     = (const float*)d_in[5];
    const float* qkv_w   = (const float*)d_in[6];
    const float* qkv_b   = (const float*)d_in[7];
    const float* out_w   = (const float*)d_in[8];
    const float* out_b   = (const float*)d_in[9];
    const float* ln1_g   = (const float*)d_in[10];
    const float* ln1_b   = (const float*)d_in[11];
    const float* ln2_g   = (const float*)d_in[12];
    const float* ln2_b   = (const float*)d_in[13];
    const float* ff1_w   = (const float*)d_in[14];
    const float* ff1_b   = (const float*)d_in[15];
    const float* ff2_w   = (const float*)d_in[16];
    const float* ff2_b   = (const float*)d_in[17];
    const float* norm_g  = (const float*)d_in[18];
    const float* norm_b  = (const float*)d_in[19];
    const float* h1_w    = (const float*)d_in[20];
    const float* h1_b    = (const float*)d_in[21];
    const float* h2_w    = (const float*)d_in[22];
    const float* h2_b    = (const float*)d_in[23];
    float* out = (float*)d_out;

    float *hbuf, *ybuf, *qkvbuf, *obuf;
    cudaGetSymbolAddress((void**)&hbuf,   g_h);
    cudaGetSymbolAddress((void**)&ybuf,   g_y);
    cudaGetSymbolAddress((void**)&qkvbuf, g_qkv);
    cudaGetSymbolAddress((void**)&obuf,   g_o);

    cudaFuncSetAttribute(half_layer,
                         cudaFuncAttributeMaxDynamicSharedMemorySize, HSM_TOTAL);

    const int rows_grid = (MROWS + 7) / 8;
    const int gm128 = (MROWS + 127) / 128;  // 941
    const int gm64  = (MROWS + 63) / 64;    // 1882

    pe_kernel<<<SS, DD>>>();
    embed_kernel<<<rows_grid, 256>>>(x, embed_w, embed_b, eln_g, eln_b, cls,
                                     ln1_g, ln1_b);

    for (int l = 0; l < LL; l++) {
        qkv_gemm<<<dim3(gm128, 3), 256>>>(ybuf, qkv_w + (size_t)l*3*DD*DD,
                                          qkv_b + l*3*DD, qkvbuf);
        attn_kernel<<<NN*HH, 320>>>(qkvbuf, obuf);
        const float* nlg = (l < LL-1) ? (ln1_g + (l+1)*DD) : nullptr;
        const float* nlb = (l < LL-1) ? (ln1_b + (l+1)*DD) : nullptr;
        half_layer<<<gm64, 256, HSM_TOTAL>>>(
            obuf, out_w + (size_t)l*DD*DD, out_b + l*DD,
            hbuf, ln2_g + l*DD, ln2_b + l*DD,
            ff1_w + (size_t)l*FFD*DD, ff1_b + l*FFD,
            ff2_w + (size_t)l*DD*FFD, ff2_b + l*DD,
            nlg, nlb, ybuf);
    }

    pool_kernel<<<1, 512>>>(norm_g, norm_b);
    head1_kernel<<<BB, DD>>>(h1_w, h1_b);
    head2_kernel<<<BB, DD>>>(h2_w, h2_b, out);
}

// round 17
// speedup vs baseline: 1.7800x; 1.1407x over previous
#include <cuda_runtime.h>
#include <cuda_bf16.h>
#include <math.h>

// Problem constants
#define BB 16
#define EE 25
#define TT 300
#define CC 3
#define DD 64
#define HH 8
#define FFD 256
#define LL 4
#define NCLS 60
#define NN (BB*EE)        // 400
#define SS (TT+1)         // 301
#define HD (DD/HH)        // 8
#define MROWS (NN*SS)     // 120400
#define EPS 1e-5f

// ---------------- scratch buffers -------------------------------------------
__device__ float g_h[MROWS*DD];      // residual stream
__device__ float g_y[MROWS*DD];      // LN output
__device__ float g_qkv[MROWS*3*DD];  // qkv
__device__ float g_o[MROWS*DD];      // attention output
__device__ float g_pe[SS*DD];        // positional encoding table
__device__ float g_feat[BB*DD];
__device__ float g_feat2[BB*DD];

// ---------------- helpers ---------------------------------------------------
__device__ __forceinline__ float warp_sum(float v) {
    #pragma unroll
    for (int o = 16; o; o >>= 1) v += __shfl_xor_sync(0xffffffffu, v, o);
    return v;
}

__device__ __forceinline__ float gelu_exact(float x) {
    return 0.5f * x * (1.0f + erff(x * 0.70710678118654752f));
}

// pack two f32 -> bf16x2 (lo = first arg)
__device__ __forceinline__ unsigned pk_bf16(float lo, float hi) {
    unsigned r;
    asm("cvt.rn.bf16x2.f32 %0, %1, %2;" : "=r"(r) : "f"(hi), "f"(lo));
    return r;
}

__device__ __forceinline__ void mma_bf16_k8(float& c0, float& c1, float& c2, float& c3,
                                            unsigned a0, unsigned a1, unsigned b0) {
    asm volatile(
        "mma.sync.aligned.m16n8k8.row.col.f32.bf16.bf16.f32 "
        "{%0,%1,%2,%3}, {%4,%5}, {%6}, {%0,%1,%2,%3};"
        : "+f"(c0), "+f"(c1), "+f"(c2), "+f"(c3)
        : "r"(a0), "r"(a1), "r"(b0));
}

__device__ __forceinline__ void mma_bf16_k16(float& c0, float& c1, float& c2, float& c3,
                                             unsigned a0, unsigned a1, unsigned a2, unsigned a3,
                                             unsigned b0, unsigned b1) {
    asm volatile(
        "mma.sync.aligned.m16n8k16.row.col.f32.bf16.bf16.f32 "
        "{%0,%1,%2,%3}, {%4,%5,%6,%7}, {%8,%9}, {%0,%1,%2,%3};"
        : "+f"(c0), "+f"(c1), "+f"(c2), "+f"(c3)
        : "r"(a0), "r"(a1), "r"(a2), "r"(a3), "r"(b0), "r"(b1));
}

// bf16-pair tiles: 32 words per row
#define ASW2(r,c) ((r)*32 + (((c) ^ (((r)&7)<<2))))

// ---------------- positional-encoding table ----------------------------------
__global__ void pe_kernel() {
    int s = blockIdx.x, d = threadIdx.x;
    const float kfreq = -0.14391565f; // -ln(10000)/64
    int i = d >> 1;
    float ang = (float)s * __expf((float)(2*i) * kfreq);
    g_pe[s*DD + d] = (d & 1) ? cosf(ang) : sinf(ang);
}

// ---------------- embed + LN + cls + pos + fused ln1[0] ----------------------
__global__ void embed_kernel(const float* __restrict__ x,
                             const float* __restrict__ ew,
                             const float* __restrict__ ebias,
                             const float* __restrict__ eg,
                             const float* __restrict__ ebt,
                             const float* __restrict__ cls,
                             const float* __restrict__ l1g,
                             const float* __restrict__ l1b) {
    int warp = (blockIdx.x * blockDim.x + threadIdx.x) >> 5;
    int lane = threadIdx.x & 31;
    if (warp >= MROWS) return;
    int n = warp / SS, s = warp % SS;
    int b = n / EE, e = n % EE;

    float v0, v1;
    if (s == 0) {
        v0 = cls[lane];
        v1 = cls[lane + 32];
    } else {
        int t = s - 1;
        float x0 = x[((b*CC + 0)*TT + t)*EE + e];
        float x1 = x[((b*CC + 1)*TT + t)*EE + e];
        float x2 = x[((b*CC + 2)*TT + t)*EE + e];
        int d0 = lane, d1 = lane + 32;
        v0 = ebias[d0] + x0*ew[d0*3] + x1*ew[d0*3+1] + x2*ew[d0*3+2];
        v1 = ebias[d1] + x0*ew[d1*3] + x1*ew[d1*3+1] + x2*ew[d1*3+2];
        float mu = warp_sum(v0 + v1) * (1.0f/64.0f);
        float a0 = v0 - mu, a1 = v1 - mu;
        float var = warp_sum(a0*a0 + a1*a1) * (1.0f/64.0f);
        float r = rsqrtf(var + EPS);
        v0 = a0 * r * eg[d0] + ebt[d0];
        v1 = a1 * r * eg[d1] + ebt[d1];
    }
    v0 += g_pe[s*DD + lane];
    v1 += g_pe[s*DD + lane + 32];

    g_h[warp*DD + lane]      = v0;
    g_h[warp*DD + lane + 32] = v1;
    // fused ln1[0]
    float mu = warp_sum(v0 + v1) * (1.0f/64.0f);
    float a0 = v0 - mu, a1 = v1 - mu;
    float var = warp_sum(a0*a0 + a1*a1) * (1.0f/64.0f);
    float rs = rsqrtf(var + EPS);
    g_y[warp*DD + lane]      = a0*rs*l1g[lane]    + l1b[lane];
    g_y[warp*DD + lane + 32] = a1*rs*l1g[lane+32] + l1b[lane+32];
}

// ---------------- qkv GEMM: bf16 k16, one N-tile per block (941 x 3) ---------
__global__ void __launch_bounds__(256, 3)
qkv_gemm(const float* __restrict__ A, const float* __restrict__ W,
         const float* __restrict__ bias, float* __restrict__ out) {
    __shared__ unsigned As[128*32];   // 16KB: 128 rows x 32 pair-words
    __shared__ unsigned Bs[64*32];    // 8KB
    int tid = threadIdx.x;
    int warp = tid >> 5, lane = tid & 31;
    int wm = warp >> 1, wn = warp & 1;
    int row0 = blockIdx.x * 128;
    int nt = blockIdx.y;
    int qr = lane >> 2, qk = lane & 3;

    #pragma unroll
    for (int i = 0; i < 8; i++) {
        int idx = tid + i*256;
        int r = idx >> 4, cp = (idx & 15) << 1;
        int gr = row0 + r;
        float4 v = (gr < MROWS) ? *(const float4*)(A + (size_t)gr*64 + 2*cp)
                                : make_float4(0.f,0.f,0.f,0.f);
        *(uint2*)(&As[ASW2(r, cp)]) =
            make_uint2(pk_bf16(v.x, v.y), pk_bf16(v.z, v.w));
    }
    #pragma unroll
    for (int i = 0; i < 4; i++) {
        int idx = tid + i*256;
        int r = idx >> 4, cp = (idx & 15) << 1;
        float4 v = *(const float4*)(W + (size_t)(nt*64 + r)*64 + 2*cp);
        *(uint2*)(&Bs[ASW2(r, cp)]) =
            make_uint2(pk_bf16(v.x, v.y), pk_bf16(v.z, v.w));
    }
    __syncthreads();

    float c[2][4][4];
    #pragma unroll
    for (int i = 0; i < 2; i++)
        #pragma unroll
        for (int j = 0; j < 4; j++)
            #pragma unroll
            for (int r = 0; r < 4; r++) c[i][j][r] = 0.f;

    #pragma unroll
    for (int kc = 0; kc < 4; kc++) {
        int kb2 = kc*8;
        unsigned a[2][4], b[4][2];
        #pragma unroll
        for (int i = 0; i < 2; i++) {
            int r = wm*32 + i*16 + qr;
            a[i][0] = As[ASW2(r,     kb2 + qk)];
            a[i][1] = As[ASW2(r + 8, kb2 + qk)];
            a[i][2] = As[ASW2(r,     kb2 + qk + 4)];
            a[i][3] = As[ASW2(r + 8, kb2 + qk + 4)];
        }
        #pragma unroll
        for (int j = 0; j < 4; j++) {
            int nn = wn*32 + j*8 + qr;
            b[j][0] = Bs[ASW2(nn, kb2 + qk)];
            b[j][1] = Bs[ASW2(nn, kb2 + qk + 4)];
        }
        #pragma unroll
        for (int i = 0; i < 2; i++)
            #pragma unroll
            for (int j = 0; j < 4; j++)
                mma_bf16_k16(c[i][j][0], c[i][j][1], c[i][j][2], c[i][j][3],
                             a[i][0], a[i][1], a[i][2], a[i][3], b[j][0], b[j][1]);
    }

    #pragma unroll
    for (int i = 0; i < 2; i++) {
        #pragma unroll
        for (int half = 0; half < 2; half++) {
            int gr = row0 + wm*32 + i*16 + qr + half*8;
            if (gr >= MROWS) continue;
            #pragma unroll
            for (int j = 0; j < 4; j++) {
                int gc = nt*64 + wn*32 + j*8 + qk*2;
                float w0 = c[i][j][half*2]     + bias[gc];
                float w1 = c[i][j][half*2 + 1] + bias[gc + 1];
                *(float2*)(out + (size_t)gr*192 + gc) = make_float2(w0, w1);
            }
        }
    }
}

// ---------------- fused half layer: bf16 operands, fp32 accum/residual -------
#define HSM_A 0
#define HSM_Z 8192
#define HSM_W 16384
#define HSM_H 24576
#define HSM_TOTAL 41472   // 24576 + 64*66*4

__global__ void __launch_bounds__(256, 3)
half_layer(const float* __restrict__ o,
           const float* __restrict__ Wout, const float* __restrict__ bout,
           float* __restrict__ h,
           const float* __restrict__ ln2g, const float* __restrict__ ln2b,
           const float* __restrict__ W1, const float* __restrict__ b1,
           const float* __restrict__ W2, const float* __restrict__ b2,
           const float* __restrict__ ln1g, const float* __restrict__ ln1b,
           float* __restrict__ y) {
    extern __shared__ __align__(16) char sm[];
    unsigned* Abuf = (unsigned*)(sm + HSM_A);   // 64x32 pair-words
    unsigned* Zbuf = (unsigned*)(sm + HSM_Z);   // 64x32 pair-words
    unsigned* Wbuf = (unsigned*)(sm + HSM_W);   // 64x32 pair-words
    float*    Hbuf = (float*)(sm + HSM_H);      // 64 x stride 66, fp32

    int tid = threadIdx.x;
    int warp = tid >> 5, lane = tid & 31;
    int wm = warp >> 1, wn = warp & 1;
    int row0 = blockIdx.x * 64;
    int qr = lane >> 2, qk = lane & 3;
    int rlo = wm*16 + qr, rhi = rlo + 8;
    int grlo = row0 + rlo, grhi = row0 + rhi;

    // ---- stage o + Wout as bf16 pairs ----
    #pragma unroll
    for (int i = 0; i < 4; i++) {
        int idx = tid + i*256;
        int r = idx >> 4, cp = (idx & 15) << 1;
        int gr = row0 + r;
        float4 v = (gr < MROWS) ? *(const float4*)(o + (size_t)gr*64 + 2*cp)
                                : make_float4(0.f,0.f,0.f,0.f);
        *(uint2*)(&Abuf[ASW2(r, cp)]) =
            make_uint2(pk_bf16(v.x, v.y), pk_bf16(v.z, v.w));
        float4 w = *(const float4*)(Wout + (size_t)r*64 + 2*cp);
        *(uint2*)(&Wbuf[ASW2(r, cp)]) =
            make_uint2(pk_bf16(w.x, w.y), pk_bf16(w.z, w.w));
    }
    __syncthreads();

    // ---- out-proj mma (bf16 k16) -> residual into Hbuf ----
    {
        float c[4][4];
        #pragma unroll
        for (int j = 0; j < 4; j++)
            #pragma unroll
            for (int r = 0; r < 4; r++) c[j][r] = 0.f;
        #pragma unroll
        for (int kc = 0; kc < 4; kc++) {
            int kb2 = kc*8;
            unsigned a0 = Abuf[ASW2(rlo, kb2 + qk)];
            unsigned a1 = Abuf[ASW2(rhi, kb2 + qk)];
            unsigned a2 = Abuf[ASW2(rlo, kb2 + qk + 4)];
            unsigned a3 = Abuf[ASW2(rhi, kb2 + qk + 4)];
            #pragma unroll
            for (int j = 0; j < 4; j++) {
                int nn = wn*32 + j*8 + qr;
                mma_bf16_k16(c[j][0], c[j][1], c[j][2], c[j][3],
                             a0, a1, a2, a3,
                             Wbuf[ASW2(nn, kb2 + qk)], Wbuf[ASW2(nn, kb2 + qk + 4)]);
            }
        }
        #pragma unroll
        for (int j = 0; j < 4; j++) {
            int gc = wn*32 + j*8 + 2*qk;
            float hv0 = c[j][0] + bout[gc], hv1 = c[j][1] + bout[gc+1];
            float hv2 = c[j][2] + bout[gc], hv3 = c[j][3] + bout[gc+1];
            if (grlo < MROWS) { float2 t = *(const float2*)(h + (size_t)grlo*64 + gc); hv0 += t.x; hv1 += t.y; }
            if (grhi < MROWS) { float2 t = *(const float2*)(h + (size_t)grhi*64 + gc); hv2 += t.x; hv3 += t.y; }
            *(float2*)(&Hbuf[rlo*66 + gc]) = make_float2(hv0, hv1);
            *(float2*)(&Hbuf[rhi*66 + gc]) = make_float2(hv2, hv3);
        }
    }
    __syncthreads();

    // ---- LN2 -> y2 (bf16 pairs) into Abuf ----
    for (int rr = warp; rr < 64; rr += 8) {
        float2 v = *(float2*)(&Hbuf[rr*66 + 2*lane]);
        float mu = warp_sum(v.x + v.y) * (1.0f/64.0f);
        float a0 = v.x - mu, a1 = v.y - mu;
        float var = warp_sum(a0*a0 + a1*a1) * (1.0f/64.0f);
        float rs = rsqrtf(var + EPS);
        float2 gg = ((const float2*)ln2g)[lane];
        float2 bb = ((const float2*)ln2b)[lane];
        Abuf[ASW2(rr, lane)] = pk_bf16(a0*rs*gg.x + bb.x, a1*rs*gg.y + bb.y);
    }
    __syncthreads();

    // ---- FF: z stays in smem (bf16) ----
    float d[4][4];
    #pragma unroll
    for (int j = 0; j < 4; j++)
        #pragma unroll
        for (int r = 0; r < 4; r++) d[j][r] = 0.f;

    for (int t = 0; t < 4; t++) {
        #pragma unroll
        for (int i = 0; i < 4; i++) {
            int idx = tid + i*256;
            int r = idx >> 4, cp = (idx & 15) << 1;
            float4 w = *(const float4*)(W1 + (size_t)(t*64 + r)*64 + 2*cp);
            *(uint2*)(&Wbuf[ASW2(r, cp)]) =
                make_uint2(pk_bf16(w.x, w.y), pk_bf16(w.z, w.w));
        }
        __syncthreads();

        float zc[4][4];
        #pragma unroll
        for (int j = 0; j < 4; j++)
            #pragma unroll
            for (int r = 0; r < 4; r++) zc[j][r] = 0.f;
        #pragma unroll
        for (int kc = 0; kc < 4; kc++) {
            int kb2 = kc*8;
            unsigned a0 = Abuf[ASW2(rlo, kb2 + qk)];
            unsigned a1 = Abuf[ASW2(rhi, kb2 + qk)];
            unsigned a2 = Abuf[ASW2(rlo, kb2 + qk + 4)];
            unsigned a3 = Abuf[ASW2(rhi, kb2 + qk + 4)];
            #pragma unroll
            for (int j = 0; j < 4; j++) {
                int nn = wn*32 + j*8 + qr;
                mma_bf16_k16(zc[j][0], zc[j][1], zc[j][2], zc[j][3],
                             a0, a1, a2, a3,
                             Wbuf[ASW2(nn, kb2 + qk)], Wbuf[ASW2(nn, kb2 + qk + 4)]);
            }
        }
        #pragma unroll
        for (int j = 0; j < 4; j++) {
            int gc = t*64 + wn*32 + j*8 + 2*qk;
            int pp = wn*16 + j*4 + qk;   // pair column
            float z0 = gelu_exact(zc[j][0] + b1[gc]);
            float z1 = gelu_exact(zc[j][1] + b1[gc+1]);
            float z2 = gelu_exact(zc[j][2] + b1[gc]);
            float z3 = gelu_exact(zc[j][3] + b1[gc+1]);
            Zbuf[ASW2(rlo, pp)] = pk_bf16(z0, z1);
            Zbuf[ASW2(rhi, pp)] = pk_bf16(z2, z3);
        }
        __syncthreads();

        #pragma unroll
        for (int i = 0; i < 4; i++) {
            int idx = tid + i*256;
            int r = idx >> 4, cp = (idx & 15) << 1;
            float4 w = *(const float4*)(W2 + (size_t)r*256 + t*64 + 2*cp);
            *(uint2*)(&Wbuf[ASW2(r, cp)]) =
                make_uint2(pk_bf16(w.x, w.y), pk_bf16(w.z, w.w));
        }
        __syncthreads();

        #pragma unroll
        for (int kc = 0; kc < 4; kc++) {
            int kb2 = kc*8;
            unsigned a0 = Zbuf[ASW2(rlo, kb2 + qk)];
            unsigned a1 = Zbuf[ASW2(rhi, kb2 + qk)];
            unsigned a2 = Zbuf[ASW2(rlo, kb2 + qk + 4)];
            unsigned a3 = Zbuf[ASW2(rhi, kb2 + qk + 4)];
            #pragma unroll
            for (int j = 0; j < 4; j++) {
                int nn = wn*32 + j*8 + qr;
                mma_bf16_k16(d[j][0], d[j][1], d[j][2], d[j][3],
                             a0, a1, a2, a3,
                             Wbuf[ASW2(nn, kb2 + qk)], Wbuf[ASW2(nn, kb2 + qk + 4)]);
            }
        }
        __syncthreads();
    }

    // ---- epilogue: hn = h' + ff2out ----
    #pragma unroll
    for (int j = 0; j < 4; j++) {
        int gc = wn*32 + j*8 + 2*qk;
        float2 hlo = *(float2*)(&Hbuf[rlo*66 + gc]);
        float2 hhi = *(float2*)(&Hbuf[rhi*66 + gc]);
        float v0 = d[j][0] + b2[gc]   + hlo.x;
        float v1 = d[j][1] + b2[gc+1] + hlo.y;
        float v2 = d[j][2] + b2[gc]   + hhi.x;
        float v3 = d[j][3] + b2[gc+1] + hhi.y;
        if (grlo < MROWS) *(float2*)(h + (size_t)grlo*64 + gc) = make_float2(v0, v1);
        if (grhi < MROWS) *(float2*)(h + (size_t)grhi*64 + gc) = make_float2(v2, v3);
        *(float2*)(&Hbuf[rlo*66 + gc]) = make_float2(v0, v1);
        *(float2*)(&Hbuf[rhi*66 + gc]) = make_float2(v2, v3);
    }

    if (ln1g == nullptr) return;
    __syncthreads();

    for (int rr = warp; rr < 64; rr += 8) {
        int grow = row0 + rr;
        if (grow >= MROWS) break;
        float2 v = *(float2*)(&Hbuf[rr*66 + 2*lane]);
        float mu = warp_sum(v.x + v.y) * (1.0f/64.0f);
        float a0 = v.x - mu, a1 = v.y - mu;
        float var = warp_sum(a0*a0 + a1*a1) * (1.0f/64.0f);
        float rs = rsqrtf(var + EPS);
        float2 gg = ((const float2*)ln1g)[lane];
        float2 bb = ((const float2*)ln1b)[lane];
        ((float2*)(y + (size_t)grow*64))[lane] =
            make_float2(a0*rs*gg.x + bb.x, a1*rs*gg.y + bb.y);
    }
}

// ---------------- bf16 flash attention (ones-mma l, full unroll) -------------
#define VROW 156   // 312 keys as bf16 pairs; stride 156 words

__global__ void __launch_bounds__(320) attn_kernel(const float* __restrict__ qkv,
                                                   float* __restrict__ o) {
    __shared__ unsigned Kb[304*4];   // K[key][d] bf16 pairs
    __shared__ unsigned Vt[8*VROW];  // V^T[d][key] bf16 pairs
    int n = blockIdx.x >> 3;
    int h = blockIdx.x & 7;
    int tid = threadIdx.x, warp = tid >> 5, lane = tid & 31;
    int gr = lane >> 2, qk = lane & 3;
    const float* base = qkv + (size_t)n*SS*(3*DD) + h*HD;

    // K stage: float4 loads, uint2 packed stores
    for (int i = tid; i < 304*2; i += 320) {
        int s = i >> 1, hf = i & 1;
        float4 v = (s < SS) ? *(const float4*)(base + (size_t)s*(3*DD) + DD + hf*4)
                            : make_float4(0.f,0.f,0.f,0.f);
        *(uint2*)(&Kb[s*4 + hf*2]) = make_uint2(pk_bf16(v.x, v.y), pk_bf16(v.z, v.w));
    }
    // V stage transposed: one key-pair per thread, float4 loads
    for (int kp = tid; kp < 152; kp += 320) {
        int s0 = 2*kp, s1 = 2*kp + 1;
        float4 va0 = make_float4(0.f,0.f,0.f,0.f), va1 = va0, vb0 = va0, vb1 = va0;
        if (s0 < SS) {
            va0 = *(const float4*)(base + (size_t)s0*(3*DD) + 2*DD);
            va1 = *(const float4*)(base + (size_t)s0*(3*DD) + 2*DD + 4);
        }
        if (s1 < SS) {
            vb0 = *(const float4*)(base + (size_t)s1*(3*DD) + 2*DD);
            vb1 = *(const float4*)(base + (size_t)s1*(3*DD) + 2*DD + 4);
        }
        Vt[0*VROW + kp] = pk_bf16(va0.x, vb0.x);
        Vt[1*VROW + kp] = pk_bf16(va0.y, vb0.y);
        Vt[2*VROW + kp] = pk_bf16(va0.z, vb0.z);
        Vt[3*VROW + kp] = pk_bf16(va0.w, vb0.w);
        Vt[4*VROW + kp] = pk_bf16(va1.x, vb1.x);
        Vt[5*VROW + kp] = pk_bf16(va1.y, vb1.y);
        Vt[6*VROW + kp] = pk_bf16(va1.z, vb1.z);
        Vt[7*VROW + kp] = pk_bf16(va1.w, vb1.w);
    }
    __syncthreads();

    const float sc = 0.35355339059327373f * 1.4426950408889634f; // 1/sqrt(8)*log2e
    const unsigned ones2 = 0x3F803F80u; // bf16x2(1.0, 1.0)

    for (int tile = warp; tile < 19; tile += 10) {
        int q0 = tile*16;
        int r0 = min(q0 + gr, SS-1);
        int r1 = min(q0 + gr + 8, SS-1);
        const float* qp0 = base + (size_t)r0*(3*DD) + 2*qk;
        const float* qp1 = base + (size_t)r1*(3*DD) + 2*qk;
        unsigned qa0 = pk_bf16(qp0[0]*sc, qp0[1]*sc);
        unsigned qa1 = pk_bf16(qp1[0]*sc, qp1[1]*sc);

        float o0=0.f, o1=0.f, o2=0.f, o3=0.f;
        float lc0=0.f, lc1=0.f, lc2=0.f, lc3=0.f;

        #pragma unroll
        for (int kt = 0; kt < 19; kt++) {
            int kb = kt*16;
            unsigned b0 = Kb[(kb + gr)*4 + qk];
            unsigned b1 = Kb[(kb + 8 + gr)*4 + qk];
            float c0=0.f, c1=0.f, c2=0.f, c3=0.f;
            float e0=0.f, e1=0.f, e2=0.f, e3=0.f;
            mma_bf16_k8(c0, c1, c2, c3, qa0, qa1, b0);
            mma_bf16_k8(e0, e1, e2, e3, qa0, qa1, b1);

            float p0, p1, p2, p3, s0, s1, s2, s3;
            asm("ex2.approx.f32 %0, %1;" : "=f"(p0) : "f"(c0));
            asm("ex2.approx.f32 %0, %1;" : "=f"(p1) : "f"(c1));
            asm("ex2.approx.f32 %0, %1;" : "=f"(p2) : "f"(c2));
            asm("ex2.approx.f32 %0, %1;" : "=f"(p3) : "f"(c3));
            asm("ex2.approx.f32 %0, %1;" : "=f"(s0) : "f"(e0));
            asm("ex2.approx.f32 %0, %1;" : "=f"(s1) : "f"(e1));
            asm("ex2.approx.f32 %0, %1;" : "=f"(s2) : "f"(e2));
            asm("ex2.approx.f32 %0, %1;" : "=f"(s3) : "f"(e3));
            if (kt == 18) {   // keys 296..303 in second n8; mask >300
                int k0i = kb + 8 + 2*qk;
                if (k0i     > 300) { s0 = 0.f; s2 = 0.f; }
                if (k0i + 1 > 300) { s1 = 0.f; s3 = 0.f; }
            }

            unsigned pa0 = pk_bf16(p0, p1);
            unsigned pa1 = pk_bf16(p2, p3);
            unsigned pa2 = pk_bf16(s0, s1);
            unsigned pa3 = pk_bf16(s2, s3);

            unsigned vb0 = Vt[gr*VROW + (kb >> 1) + qk];
            unsigned vb1 = Vt[gr*VROW + (kb >> 1) + 4 + qk];
            mma_bf16_k16(o0, o1, o2, o3, pa0, pa1, pa2, pa3, vb0, vb1);
            mma_bf16_k16(lc0, lc1, lc2, lc3, pa0, pa1, pa2, pa3, ones2, ones2);
        }

        float inv0 = 1.0f / lc0, inv1 = 1.0f / lc2;

        int row0g = q0 + gr, row1g = q0 + gr + 8;
        if (row0g < SS)
            *(float2*)(o + ((size_t)n*SS + row0g)*DD + h*HD + 2*qk) =
                make_float2(o0*inv0, o1*inv0);
        if (row1g < SS)
            *(float2*)(o + ((size_t)n*SS + row1g)*DD + h*HD + 2*qk) =
                make_float2(o2*inv1, o3*inv1);
    }
}

// ---------------- cls pool over edges + LayerNorm ----------------------------
__global__ void pool_kernel(const float* __restrict__ g, const float* __restrict__ bt) {
    int warp = threadIdx.x >> 5;
    int lane = threadIdx.x & 31;
    if (warp >= BB) return;
    int b = warp;
    float v0 = 0.f, v1 = 0.f;
    for (int e = 0; e < EE; e++) {
        size_t base = ((size_t)(b*EE + e)*SS)*DD;
        v0 += g_h[base + lane];
        v1 += g_h[base + lane + 32];
    }
    v0 *= (1.0f/EE); v1 *= (1.0f/EE);
    float mu = warp_sum(v0 + v1) * (1.0f/64.0f);
    float a0 = v0 - mu, a1 = v1 - mu;
    float var = warp_sum(a0*a0 + a1*a1) * (1.0f/64.0f);
    float rs = rsqrtf(var + EPS);
    g_feat[b*DD + lane]    = a0*rs*g[lane]    + bt[lane];
    g_feat[b*DD + lane+32] = a1*rs*g[lane+32] + bt[lane+32];
}

// ---------------- head MLP ---------------------------------------------------
__global__ void head1_kernel(const float* __restrict__ w, const float* __restrict__ bias) {
    __shared__ float f[DD];
    int b = blockIdx.x, d = threadIdx.x;
    f[d] = g_feat[b*DD + d];
    __syncthreads();
    float acc = bias[d];
    #pragma unroll 8
    for (int k = 0; k < DD; k++) acc = fmaf(f[k], w[d*DD + k], acc);
    g_feat2[b*DD + d] = gelu_exact(acc);
}

__global__ void head2_kernel(const float* __restrict__ w, const float* __restrict__ bias,
                             float* __restrict__ out) {
    __shared__ float f[DD];
    int b = blockIdx.x, c = threadIdx.x;
    f[c] = g_feat2[b*DD + c];
    __syncthreads();
    if (c >= NCLS) return;
    float acc = bias[c];
    #pragma unroll 8
    for (int k = 0; k < DD; k++) acc = fmaf(f[k], w[c*DD + k], acc);
    out[b*NCLS + c] = acc;
}

// ---------------- launcher ---------------------------------------------------
extern "C" void kernel_launch(void* const* d_in, const int* in_sizes, int n_in,
                              void* d_out, int out_size) {
    const float* x       = (const float*)d_in[0];
    const float* embed_w = (const float*)d_in[1];
    const float* embed_b = (const float*)d_in[2];
    const float* eln_g   = (const float*)d_in[3];
    const float* eln_b   = (const float*)d_in[4];
    const float* cls     = (const float*)d_in[5];
    const float* qkv_w   = (const float*)d_in[6];
    const float* qkv_b   = (const float*)d_in[7];
    const float* out_w   = (const float*)d_in[8];
    const float* out_b   = (const float*)d_in[9];
    const float* ln1_g   = (const float*)d_in[10];
    const float* ln1_b   = (const float*)d_in[11];
    const float* ln2_g   = (const float*)d_in[12];
    const float* ln2_b   = (const float*)d_in[13];
    const float* ff1_w   = (const float*)d_in[14];
    const float* ff1_b   = (const float*)d_in[15];
    const float* ff2_w   = (const float*)d_in[16];
    const float* ff2_b   = (const float*)d_in[17];
    const float* norm_g  = (const float*)d_in[18];
    const float* norm_b  = (const float*)d_in[19];
    const float* h1_w    = (const float*)d_in[20];
    const float* h1_b    = (const float*)d_in[21];
    const float* h2_w    = (const float*)d_in[22];
    const float* h2_b    = (const float*)d_in[23];
    float* out = (float*)d_out;

    float *hbuf, *ybuf, *qkvbuf, *obuf;
    cudaGetSymbolAddress((void**)&hbuf,   g_h);
    cudaGetSymbolAddress((void**)&ybuf,   g_y);
    cudaGetSymbolAddress((void**)&qkvbuf, g_qkv);
    cudaGetSymbolAddress((void**)&obuf,   g_o);

    cudaFuncSetAttribute(half_layer,
                         cudaFuncAttributeMaxDynamicSharedMemorySize, HSM_TOTAL);

    const int rows_grid = (MROWS + 7) / 8;
    const int gm128 = (MROWS + 127) / 128;  // 941
    const int gm64  = (MROWS + 63) / 64;    // 1882

    pe_kernel<<<SS, DD>>>();
    embed_kernel<<<rows_grid, 256>>>(x, embed_w, embed_b, eln_g, eln_b, cls,
                                     ln1_g, ln1_b);

    for (int l = 0; l < LL; l++) {
        qkv_gemm<<<dim3(gm128, 3), 256>>>(ybuf, qkv_w + (size_t)l*3*DD*DD,
                                          qkv_b + l*3*DD, qkvbuf);
        attn_kernel<<<NN*HH, 320>>>(qkvbuf, obuf);
        const float* nlg = (l < LL-1) ? (ln1_g + (l+1)*DD) : nullptr;
        const float* nlb = (l < LL-1) ? (ln1_b + (l+1)*DD) : nullptr;
        half_layer<<<gm64, 256, HSM_TOTAL>>>(
            obuf, out_w + (size_t)l*DD*DD, out_b + l*DD,
            hbuf, ln2_g + l*DD, ln2_b + l*DD,
            ff1_w + (size_t)l*FFD*DD, ff1_b + l*FFD,
            ff2_w + (size_t)l*DD*FFD, ff2_b + l*DD,
            nlg, nlb, ybuf);
    }

    pool_kernel<<<1, 512>>>(norm_g, norm_b);
    head1_kernel<<<BB, DD>>>(h1_w, h1_b);
    head2_kernel<<<BB, DD>>>(h2_w, h2_b, out);
}